// round 14
// baseline (speedup 1.0000x reference)
#include <cuda_runtime.h>
#include <cuda_fp16.h>
#include <stdint.h>
#include <math.h>

#define B_DIM   8
#define C_DIM   256
#define N_PIX   4096
#define EPS     1e-6f
#define CN      ((size_t)C_DIM * N_PIX)
#define NN      ((size_t)N_PIX * N_PIX)

// ---------------- scratch (__device__ globals; no allocation allowed) -----
__device__ __half g_h_hi[(size_t)B_DIM * CN];   // h^T  [B][N][C]
__device__ __half g_h_lo[(size_t)B_DIM * CN];
__device__ __half g_q_hi[(size_t)B_DIM * CN];   // q^T  [B][N][C] (pre-scaled 1/16)
__device__ __half g_q_lo[(size_t)B_DIM * CN];
__device__ __half g_k_hi[(size_t)B_DIM * CN];   // k^T  [B][N][C]
__device__ __half g_k_lo[(size_t)B_DIM * CN];
__device__ __half g_v_hi[(size_t)B_DIM * CN];   // v    [B][C][N]
__device__ __half g_v_lo[(size_t)B_DIM * CN];
__device__ __half g_z_hi[(size_t)B_DIM * CN];   // z^T  [B][N][C]
__device__ __half g_z_lo[(size_t)B_DIM * CN];
__device__ __half g_p  [(size_t)B_DIM * NN];    // P = exp(S - 5), fp16
__device__ __half g_w_hi[4][C_DIM * C_DIM];     // wq, wk, wv, wo
__device__ __half g_w_lo[4][C_DIM * C_DIM];

// ---------------- PTX helpers ---------------------------------------------
__device__ __forceinline__ uint32_t s2u(const void* p) {
    uint32_t a;
    asm("{ .reg .u64 t; cvta.to.shared.u64 t, %1; cvt.u32.u64 %0, t; }" : "=r"(a) : "l"(p));
    return a;
}
__device__ __forceinline__ void cp16(uint32_t s, const void* g) {
    asm volatile("cp.async.cg.shared.global [%0], [%1], 16;" :: "r"(s), "l"(g));
}
__device__ __forceinline__ void cp_commit() { asm volatile("cp.async.commit_group;" ::: "memory"); }
__device__ __forceinline__ void cp_wait1()  { asm volatile("cp.async.wait_group 1;" ::: "memory"); }
__device__ __forceinline__ void cp_wait0()  { asm volatile("cp.async.wait_group 0;" ::: "memory"); }

__device__ __forceinline__ void ldsm4(uint32_t* r, uint32_t addr) {
    asm volatile("ldmatrix.sync.aligned.m8n8.x4.shared.b16 {%0,%1,%2,%3}, [%4];"
        : "=r"(r[0]), "=r"(r[1]), "=r"(r[2]), "=r"(r[3]) : "r"(addr));
}
__device__ __forceinline__ void mma2(float* d, const uint32_t* a, uint32_t b0, uint32_t b1) {
    asm volatile("mma.sync.aligned.m16n8k16.row.col.f32.f16.f16.f32 "
        "{%0,%1,%2,%3}, {%4,%5,%6,%7}, {%8,%9}, {%0,%1,%2,%3};"
        : "+f"(d[0]), "+f"(d[1]), "+f"(d[2]), "+f"(d[3])
        : "r"(a[0]), "r"(a[1]), "r"(a[2]), "r"(a[3]), "r"(b0), "r"(b1));
}

__device__ __forceinline__ void split2(float v0, float v1, __half2& h, __half2& l) {
    __half h0 = __float2half_rn(v0), h1 = __float2half_rn(v1);
    h = __halves2half2(h0, h1);
    l = __halves2half2(__float2half_rn(v0 - __half2float(h0)),
                       __float2half_rn(v1 - __half2float(h1)));
}

// ---------------- CTA GEMM: 128x128 tile, 8 warps, BK=32, split fp16 -------
// TERMS==3: a_hi*b_hi + a_hi*b_lo + a_lo*b_hi; TERMS==2: a_hi*(b_hi+b_lo)
// SMEM stage: A_hi [+A_lo if 3-term] + B_hi + B_lo tiles, 10240B each.
#define TILE_B 10240
template<int TERMS> struct StageCfg {
    static const int ALO = 10240;                       // 3-term only
    static const int BHI = (TERMS == 3) ? 20480 : 10240;
    static const int BLO = BHI + 10240;
    static const int BYTES = (TERMS == 3) ? 40960 : 30720;
};
#define SMEM_MMA3 (2 * 40960)
#define SMEM_MMA2 (2 * 30720)

template<int TERMS>
__device__ __forceinline__ void load_chunk(char* sm, int stage,
    const __half* __restrict__ Ahi, const __half* __restrict__ Alo, int lda,
    const __half* __restrict__ Bhi, const __half* __restrict__ Blo, int ldb,
    int k0, int tid)
{
    uint32_t base = s2u(sm) + stage * StageCfg<TERMS>::BYTES;
    #pragma unroll
    for (int it = 0; it < 2; it++) {
        int idx = tid + it * 256;          // 0..511
        int r = idx >> 2, g = idx & 3;     // row, 16B-group
        uint32_t so = r * 80 + g * 16;
        size_t ga = (size_t)r * lda + k0 + g * 8;
        size_t gb = (size_t)r * ldb + k0 + g * 8;
        cp16(base + so, Ahi + ga);
        if (TERMS == 3) cp16(base + StageCfg<TERMS>::ALO + so, Alo + ga);
        cp16(base + StageCfg<TERMS>::BHI + so, Bhi + gb);
        cp16(base + StageCfg<TERMS>::BLO + so, Blo + gb);
    }
    cp_commit();
}

template<int TERMS>
__device__ __forceinline__ void compute_chunk(uint32_t sbase, float (&acc)[16][4],
                                              int wm, int wn, int lane)
{
    const int lrow  = (lane & 7) + ((lane & 8) ? 8 : 0);
    const int lcolo = (lane & 16) ? 8 : 0;
    #pragma unroll
    for (int ks = 0; ks < 2; ks++) {
        const int col = ks * 16 + lcolo;
        uint32_t ahi[4][4], alo[4][4];
        #pragma unroll
        for (int mt = 0; mt < 4; mt++) {
            uint32_t off = (uint32_t)(wm * 64 + mt * 16 + lrow) * 80 + col * 2;
            ldsm4(ahi[mt], sbase + off);
            if (TERMS == 3) ldsm4(alo[mt], sbase + StageCfg<TERMS>::ALO + off);
        }
        #pragma unroll
        for (int np = 0; np < 2; np++) {
            uint32_t off = (uint32_t)(wn * 32 + np * 16 + lrow) * 80 + col * 2;
            uint32_t th[4], tl[4];
            ldsm4(th, sbase + StageCfg<TERMS>::BHI + off);
            ldsm4(tl, sbase + StageCfg<TERMS>::BLO + off);
            // consume B fragments in place: pair0 = (th0,th2), pair1 = (th1,th3)
            #pragma unroll
            for (int mt = 0; mt < 4; mt++) {
                float* d0 = acc[mt * 4 + 2 * np];
                float* d1 = acc[mt * 4 + 2 * np + 1];
                mma2(d0, ahi[mt], th[0], th[2]);
                mma2(d0, ahi[mt], tl[0], tl[2]);
                if (TERMS == 3) mma2(d0, alo[mt], th[0], th[2]);
                mma2(d1, ahi[mt], th[1], th[3]);
                mma2(d1, ahi[mt], tl[1], tl[3]);
                if (TERMS == 3) mma2(d1, alo[mt], th[1], th[3]);
            }
        }
    }
}

template<int TERMS>
__device__ void gemm_tile(char* sm,
    const __half* Ahi, const __half* Alo, int lda,
    const __half* Bhi, const __half* Blo, int ldb,
    int K, float (&acc)[16][4])
{
    const int tid = threadIdx.x;
    const int lane = tid & 31, warp = tid >> 5;
    const int wm = warp >> 2, wn = warp & 3;
    #pragma unroll
    for (int f = 0; f < 16; f++)
        acc[f][0] = acc[f][1] = acc[f][2] = acc[f][3] = 0.f;

    const int NC = K >> 5;
    load_chunk<TERMS>(sm, 0, Ahi, Alo, lda, Bhi, Blo, ldb, 0, tid);
    if (NC > 1) load_chunk<TERMS>(sm, 1, Ahi, Alo, lda, Bhi, Blo, ldb, 32, tid);
    const uint32_t smb = s2u(sm);

    for (int c = 0; c < NC; c++) {
        if (c + 1 < NC) cp_wait1(); else cp_wait0();
        __syncthreads();
        compute_chunk<TERMS>(smb + (c & 1) * StageCfg<TERMS>::BYTES, acc, wm, wn, lane);
        __syncthreads();
        if (c + 2 < NC)
            load_chunk<TERMS>(sm, c & 1, Ahi, Alo, lda, Bhi, Blo, ldb, (c + 2) * 32, tid);
    }
}

// ---------------- weight convert (all 4 in one launch) --------------------
__global__ void __launch_bounds__(256) convert_w(const float* __restrict__ wq,
                                                 const float* __restrict__ wk,
                                                 const float* __restrict__ wv,
                                                 const float* __restrict__ wo) {
    const int which = blockIdx.y;
    const float* w = (which == 0) ? wq : (which == 1) ? wk : (which == 2) ? wv : wo;
    int i = blockIdx.x * 256 + threadIdx.x;
    float v = w[i];
    __half h = __float2half_rn(v);
    g_w_hi[which][i] = h;
    g_w_lo[which][i] = __float2half_rn(v - __half2float(h));
}

// ---------------- GroupNorm -> h^T split ----------------------------------
__global__ void __launch_bounds__(256) gn_kernel(const float* __restrict__ x,
                                                 const float* __restrict__ sc,
                                                 const float* __restrict__ bi) {
    __shared__ float tile[8][1028];
    __shared__ float red[256], red2[256];
    const int bg = blockIdx.x;
    const int b = bg >> 5, g = bg & 31;
    const float* xb = x + (size_t)b * CN + (size_t)(g * 8) * N_PIX;
    const int t = threadIdx.x;

    float s = 0.f, s2 = 0.f;
    for (int i = t; i < 8 * N_PIX; i += 256) {
        float v = xb[i];
        s += v; s2 += v * v;
    }
    red[t] = s; red2[t] = s2;
    __syncthreads();
    for (int o = 128; o > 0; o >>= 1) {
        if (t < o) { red[t] += red[t + o]; red2[t] += red2[t + o]; }
        __syncthreads();
    }
    const float mean = red[0] * (1.f / 32768.f);
    const float var  = red2[0] * (1.f / 32768.f) - mean * mean;
    const float inv  = rsqrtf(var + EPS);
    float scv[8], biv[8];
    #pragma unroll
    for (int c = 0; c < 8; c++) { scv[c] = sc[g * 8 + c] * inv; biv[c] = bi[g * 8 + c]; }

    for (int p0 = 0; p0 < N_PIX; p0 += 1024) {
        __syncthreads();
        for (int i = t; i < 8192; i += 256) {
            int c = i >> 10, pp = i & 1023;
            tile[c][pp] = xb[(size_t)c * N_PIX + p0 + pp];
        }
        __syncthreads();
        #pragma unroll
        for (int j = 0; j < 4; j++) {
            int p = t + j * 256;
            int ip = p0 + p;
            uint32_t ph[4], pl[4];
            #pragma unroll
            for (int c2 = 0; c2 < 4; c2++) {
                float a  = (tile[2*c2][p]   - mean) * scv[2*c2]   + biv[2*c2];
                float b2 = (tile[2*c2+1][p] - mean) * scv[2*c2+1] + biv[2*c2+1];
                __half2 h, l;
                split2(a, b2, h, l);
                ph[c2] = *(uint32_t*)&h;
                pl[c2] = *(uint32_t*)&l;
            }
            size_t base = ((size_t)b * N_PIX + ip) * C_DIM + g * 8;
            *(uint4*)&g_h_hi[base] = make_uint4(ph[0], ph[1], ph[2], ph[3]);
            *(uint4*)&g_h_lo[base] = make_uint4(pl[0], pl[1], pl[2], pl[3]);
        }
    }
}

// ---------------- q/k projection: D[i,o] = sum_c hT[i,c] w[o,c] -----------
__global__ void __launch_bounds__(256) proj_qk(const float* __restrict__ bq,
                                               const float* __restrict__ bk) {
    extern __shared__ char sm[];
    const int mt_ = blockIdx.x, nt_ = blockIdx.y;
    const int b = blockIdx.z >> 1, p = blockIdx.z & 1;
    const size_t abase = ((size_t)b * N_PIX + mt_ * 128) * C_DIM;
    const __half* Whi = (p ? g_w_hi[1] : g_w_hi[0]) + (size_t)nt_ * 128 * C_DIM;
    const __half* Wlo = (p ? g_w_lo[1] : g_w_lo[0]) + (size_t)nt_ * 128 * C_DIM;

    float acc[16][4];
    gemm_tile<3>(sm, g_h_hi + abase, g_h_lo + abase, C_DIM, Whi, Wlo, C_DIM, C_DIM, acc);

    const float* bias = p ? bk : bq;
    const float scale = p ? 1.0f : 0.0625f;
    __half* Ohi = (p ? g_k_hi : g_q_hi) + abase;
    __half* Olo = (p ? g_k_lo : g_q_lo) + abase;
    const int lane = threadIdx.x & 31, warp = threadIdx.x >> 5;
    const int wm = warp >> 2, wn = warp & 3;
    #pragma unroll
    for (int mt = 0; mt < 4; mt++)
        #pragma unroll
        for (int nt = 0; nt < 4; nt++) {
            const int m = wm * 64 + mt * 16 + (lane >> 2);
            const int n = wn * 32 + nt * 8 + (lane & 3) * 2;
            const int o = nt_ * 128 + n;
            const float b0 = bias[o], b1 = bias[o + 1];
            const float* d = acc[mt * 4 + nt];
            #pragma unroll
            for (int rp = 0; rp < 2; rp++) {
                const int row = m + rp * 8;
                __half2 h, l;
                split2((d[rp*2+0] + b0) * scale, (d[rp*2+1] + b1) * scale, h, l);
                const size_t off = (size_t)row * C_DIM + o;
                *(__half2*)&Ohi[off] = h;
                *(__half2*)&Olo[off] = l;
            }
        }
}

// ---------------- v projection: D[o,i] = sum_c wv[o,c] hT[i,c] ------------
__global__ void __launch_bounds__(256, 3) proj_v(const float* __restrict__ bv) {
    extern __shared__ char sm[];
    const int mt_ = blockIdx.x, nt_ = blockIdx.y, b = blockIdx.z;
    const size_t bbase = ((size_t)b * N_PIX + nt_ * 128) * C_DIM;

    float acc[16][4];
    gemm_tile<2>(sm, g_w_hi[2] + (size_t)mt_ * 128 * C_DIM,
                 g_w_lo[2] + (size_t)mt_ * 128 * C_DIM, C_DIM,
                 g_h_hi + bbase, g_h_lo + bbase, C_DIM, C_DIM, acc);

    const int lane = threadIdx.x & 31, warp = threadIdx.x >> 5;
    const int wm = warp >> 2, wn = warp & 3;
    #pragma unroll
    for (int mt = 0; mt < 4; mt++)
        #pragma unroll
        for (int nt = 0; nt < 4; nt++) {
            const int m = wm * 64 + mt * 16 + (lane >> 2);
            const int n = wn * 32 + nt * 8 + (lane & 3) * 2;
            const int pix = nt_ * 128 + n;
            const float* d = acc[mt * 4 + nt];
            #pragma unroll
            for (int rp = 0; rp < 2; rp++) {
                const int o = mt_ * 128 + m + rp * 8;
                const float bb = bv[o];
                __half2 h, l;
                split2(d[rp*2+0] + bb, d[rp*2+1] + bb, h, l);
                const size_t off = ((size_t)b * C_DIM + o) * N_PIX + pix;
                *(__half2*)&g_v_hi[off] = h;
                *(__half2*)&g_v_lo[off] = l;
            }
        }
}

// ---------------- scores+exp: P[i,j] = exp(sum_c qT[i,c] kT[j,c] - 5) -----
// 2-term: q_hi * (k_hi + k_lo)
__global__ void __launch_bounds__(256, 3) scores_k() {
    extern __shared__ char sm[];
    const int mt_ = blockIdx.x, nt_ = blockIdx.y, b = blockIdx.z;
    const size_t abase = ((size_t)b * N_PIX + mt_ * 128) * C_DIM;
    const size_t bbase = ((size_t)b * N_PIX + nt_ * 128) * C_DIM;

    float acc[16][4];
    gemm_tile<2>(sm, g_q_hi + abase, g_q_lo + abase, C_DIM,
                 g_k_hi + bbase, g_k_lo + bbase, C_DIM, C_DIM, acc);

    __half* Pm = g_p + (size_t)b * NN;
    const int lane = threadIdx.x & 31, warp = threadIdx.x >> 5;
    const int wm = warp >> 2, wn = warp & 3;
    #pragma unroll
    for (int mt = 0; mt < 4; mt++)
        #pragma unroll
        for (int nt = 0; nt < 4; nt++) {
            const int m = wm * 64 + mt * 16 + (lane >> 2);
            const int n = wn * 32 + nt * 8 + (lane & 3) * 2;
            const int j = nt_ * 128 + n;
            const float* d = acc[mt * 4 + nt];
            #pragma unroll
            for (int rp = 0; rp < 2; rp++) {
                const int i = mt_ * 128 + m + rp * 8;
                const float p0 = __expf(d[rp*2+0] - 5.f);
                const float p1 = __expf(d[rp*2+1] - 5.f);
                __half2 hp = __halves2half2(__float2half_rn(p0), __float2half_rn(p1));
                *(__half2*)&Pm[(size_t)i * N_PIX + j] = hp;
            }
        }
}

// ---------------- fused normalize + PV (V hi+lo, 2-term) ------------------
// z[i,c] = (sum_j P[i,j] v[c,j]) / (sum_j P[i,j]),  P fp16 from scores_k.
// 512 threads: warp grid 4x4, warp tile 32 rows x 64 cols. 32-key chunks.
#define SZ_PBASE 512
#define SZ_VBASE 20992
#define SZ_SMEM  102912

__device__ __forceinline__ void sz_load(uint32_t smb, const __half* P,
    const __half* Vhi, const __half* Vlo, int st, int j0, int tid)
{
    uint32_t pb = smb + SZ_PBASE + st * 10240;
    {
        int r = tid >> 2, g = tid & 3;            // i-row, 16B group (32 halves/row)
        cp16(pb + r * 80 + g * 16, P + (size_t)r * N_PIX + j0 + g * 8);
    }
    uint32_t vb = smb + SZ_VBASE + st * 40960;
    #pragma unroll
    for (int it = 0; it < 2; it++) {
        int idx = tid + it * 512;
        int r = idx >> 2, g = idx & 3;            // c-row, 16B group
        size_t go = (size_t)r * N_PIX + j0 + g * 8;
        cp16(vb + r * 80 + g * 16, Vhi + go);
        cp16(vb + 20480 + r * 80 + g * 16, Vlo + go);
    }
    cp_commit();
}

__device__ __forceinline__ void sz_compute(uint32_t sP, uint32_t sVhi, uint32_t sVlo,
                                           float (&acc)[16][4], int wm, int wn, int lane)
{
    const int lrow  = (lane & 7) + ((lane & 8) ? 8 : 0);
    const int lcolo = (lane & 16) ? 8 : 0;
    #pragma unroll
    for (int ks = 0; ks < 2; ks++) {
        const int col = ks * 16 + lcolo;
        uint32_t a[2][4];
        #pragma unroll
        for (int mt = 0; mt < 2; mt++)
            ldsm4(a[mt], sP + (uint32_t)(wm * 32 + mt * 16 + lrow) * 80 + col * 2);
        #pragma unroll
        for (int np = 0; np < 4; np++) {
            uint32_t off = (uint32_t)(wn * 64 + np * 16 + lrow) * 80 + col * 2;
            uint32_t th[4], tl[4];
            ldsm4(th, sVhi + off);
            ldsm4(tl, sVlo + off);
            #pragma unroll
            for (int mt = 0; mt < 2; mt++) {
                float* d0 = acc[mt * 8 + 2 * np];
                float* d1 = acc[mt * 8 + 2 * np + 1];
                mma2(d0, a[mt], th[0], th[2]);
                mma2(d0, a[mt], tl[0], tl[2]);
                mma2(d1, a[mt], th[1], th[3]);
                mma2(d1, a[mt], tl[1], tl[3]);
            }
        }
    }
}

__global__ void __launch_bounds__(512, 1) sz_k() {
    extern __shared__ char sm[];
    const int mt_ = blockIdx.x, b = blockIdx.z;
    const int tid = threadIdx.x, lane = tid & 31, warp = tid >> 5;
    const int wm = warp >> 2, wn = warp & 3;
    const uint32_t smb = s2u(sm);

    const __half* P = g_p + (size_t)b * NN + (size_t)(mt_ * 128) * N_PIX;
    const __half* Vhi = g_v_hi + (size_t)b * CN;
    const __half* Vlo = g_v_lo + (size_t)b * CN;

    float acc[16][4];
    #pragma unroll
    for (int f = 0; f < 16; f++)
        acc[f][0] = acc[f][1] = acc[f][2] = acc[f][3] = 0.f;
    float rsum = 0.f;

    const int pr = tid >> 2, pq = tid & 3;        // rowsum: row, 16B quarter

    sz_load(smb, P, Vhi, Vlo, 0, 0, tid);
    sz_load(smb, P, Vhi, Vlo, 1, 32, tid);

    const int NC = N_PIX / 32;   // 128
    for (int c = 0; c < NC; c++) {
        const int st = c & 1;
        if (c + 1 < NC) cp_wait1(); else cp_wait0();
        __syncthreads();
        {
            const uint4 pv = *(const uint4*)(sm + SZ_PBASE + st * 10240 + pr * 80 + pq * 16);
            float2 f0 = __half22float2(*(const __half2*)&pv.x);
            float2 f1 = __half22float2(*(const __half2*)&pv.y);
            float2 f2 = __half22float2(*(const __half2*)&pv.z);
            float2 f3 = __half22float2(*(const __half2*)&pv.w);
            rsum += (f0.x + f0.y) + (f1.x + f1.y) + (f2.x + f2.y) + (f3.x + f3.y);
        }
        sz_compute(smb + SZ_PBASE + st * 10240,
                   smb + SZ_VBASE + st * 40960,
                   smb + SZ_VBASE + st * 40960 + 20480, acc, wm, wn, lane);
        __syncthreads();
        if (c + 2 < NC) sz_load(smb, P, Vhi, Vlo, st, (c + 2) * 32, tid);
    }

    // ---- finalize row sums (4 threads per row -> smem) ----
    rsum += __shfl_xor_sync(0xffffffffu, rsum, 1);
    rsum += __shfl_xor_sync(0xffffffffu, rsum, 2);
    if (pq == 0) ((float*)sm)[pr] = rsum;
    __syncthreads();
    const float* rs = (const float*)sm;

    // ---- epilogue: normalize + split-store z^T ----
    #pragma unroll
    for (int mt = 0; mt < 2; mt++) {
        const int m = wm * 32 + mt * 16 + (lane >> 2);
        const float invA = 1.f / rs[m];
        const float invB = 1.f / rs[m + 8];
        #pragma unroll
        for (int nt = 0; nt < 8; nt++) {
            const int cc = wn * 64 + nt * 8 + (lane & 3) * 2;
            const float* d = acc[mt * 8 + nt];
            __half2 h, l;
            split2(d[0] * invA, d[1] * invA, h, l);
            size_t off = ((size_t)b * N_PIX + mt_ * 128 + m) * C_DIM + cc;
            *(__half2*)&g_z_hi[off] = h;
            *(__half2*)&g_z_lo[off] = l;
            split2(d[2] * invB, d[3] * invB, h, l);
            off = ((size_t)b * N_PIX + mt_ * 128 + m + 8) * C_DIM + cc;
            *(__half2*)&g_z_hi[off] = h;
            *(__half2*)&g_z_lo[off] = l;
        }
    }
}

// ---------------- out: D[o,i] = sum_c wo[o,c] zT[i,c]; + bo + skip --------
__global__ void __launch_bounds__(256, 3) out_k(const float* __restrict__ bo,
                                                const float* __restrict__ x,
                                                float* __restrict__ out) {
    extern __shared__ char sm[];
    const int mt_ = blockIdx.x, nt_ = blockIdx.y, b = blockIdx.z;
    const size_t bbase = ((size_t)b * N_PIX + nt_ * 128) * C_DIM;

    float acc[16][4];
    gemm_tile<2>(sm, g_w_hi[3] + (size_t)mt_ * 128 * C_DIM,
                 g_w_lo[3] + (size_t)mt_ * 128 * C_DIM, C_DIM,
                 g_z_hi + bbase, g_z_lo + bbase, C_DIM, C_DIM, acc);

    const int lane = threadIdx.x & 31, warp = threadIdx.x >> 5;
    const int wm = warp >> 2, wn = warp & 3;
    #pragma unroll
    for (int mt = 0; mt < 4; mt++)
        #pragma unroll
        for (int nt = 0; nt < 4; nt++) {
            const int m = wm * 64 + mt * 16 + (lane >> 2);
            const int n = wn * 32 + nt * 8 + (lane & 3) * 2;
            const int i = nt_ * 128 + n;
            const float* d = acc[mt * 4 + nt];
            #pragma unroll
            for (int rp = 0; rp < 2; rp++) {
                const int o = mt_ * 128 + m + rp * 8;
                const float bb = bo[o];
                const size_t off = ((size_t)b * C_DIM + o) * N_PIX + i;
                float2 sk = *(const float2*)&x[off];
                *(float2*)&out[off] = make_float2(d[rp*2+0] + bb + sk.x,
                                                  d[rp*2+1] + bb + sk.y);
            }
        }
}

// ---------------- launch ---------------------------------------------------
extern "C" void kernel_launch(void* const* d_in, const int* in_sizes, int n_in,
                              void* d_out, int out_size) {
    const float* x  = (const float*)d_in[0];
    const float* gs = (const float*)d_in[1];
    const float* gb = (const float*)d_in[2];
    const float* wq = (const float*)d_in[3];
    const float* bq = (const float*)d_in[4];
    const float* wk = (const float*)d_in[5];
    const float* bk = (const float*)d_in[6];
    const float* wv = (const float*)d_in[7];
    const float* bv = (const float*)d_in[8];
    const float* wo = (const float*)d_in[9];
    const float* bo = (const float*)d_in[10];
    float* out = (float*)d_out;

    cudaFuncSetAttribute(proj_qk,  cudaFuncAttributeMaxDynamicSharedMemorySize, SMEM_MMA3);
    cudaFuncSetAttribute(proj_v,   cudaFuncAttributeMaxDynamicSharedMemorySize, SMEM_MMA2);
    cudaFuncSetAttribute(scores_k, cudaFuncAttributeMaxDynamicSharedMemorySize, SMEM_MMA2);
    cudaFuncSetAttribute(sz_k,     cudaFuncAttributeMaxDynamicSharedMemorySize, SZ_SMEM);
    cudaFuncSetAttribute(out_k,    cudaFuncAttributeMaxDynamicSharedMemorySize, SMEM_MMA2);

    convert_w<<<dim3(256, 4), 256>>>(wq, wk, wv, wo);
    gn_kernel<<<B_DIM * 32, 256>>>(x, gs, gb);
    proj_qk<<<dim3(32, 2, B_DIM * 2), 256, SMEM_MMA3>>>(bq, bk);
    proj_v<<<dim3(2, 32, B_DIM), 256, SMEM_MMA2>>>(bv);
    scores_k<<<dim3(32, 32, B_DIM), 256, SMEM_MMA2>>>();
    sz_k<<<dim3(32, 1, B_DIM), 512, SZ_SMEM>>>();
    out_k<<<dim3(2, 32, B_DIM), 256, SMEM_MMA2>>>(bo, x, out);
}

// round 15
// speedup vs baseline: 1.1551x; 1.1551x over previous
#include <cuda_runtime.h>
#include <cuda_fp16.h>
#include <stdint.h>
#include <math.h>

#define B_DIM   8
#define C_DIM   256
#define N_PIX   4096
#define EPS     1e-6f
#define CN      ((size_t)C_DIM * N_PIX)
#define NN      ((size_t)N_PIX * N_PIX)

// ---------------- scratch (__device__ globals; no allocation allowed) -----
__device__ __half g_h_hi[(size_t)B_DIM * CN];   // h^T  [B][N][C]
__device__ __half g_h_lo[(size_t)B_DIM * CN];
__device__ __half g_q_hi[(size_t)B_DIM * CN];   // q^T  [B][N][C] (pre-scaled 1/16)
__device__ __half g_q_lo[(size_t)B_DIM * CN];
__device__ __half g_k_hi[(size_t)B_DIM * CN];   // k^T  [B][N][C]
__device__ __half g_k_lo[(size_t)B_DIM * CN];
__device__ __half g_v_hi[(size_t)B_DIM * CN];   // v    [B][C][N]
__device__ __half g_v_lo[(size_t)B_DIM * CN];
__device__ __half g_z_hi[(size_t)B_DIM * CN];   // z^T  [B][N][C]
__device__ __half g_z_lo[(size_t)B_DIM * CN];
__device__ __half g_p  [(size_t)B_DIM * NN];    // P = exp(S - 5), fp16
__device__ __half g_w_hi[4][C_DIM * C_DIM];     // wq, wk, wv, wo
__device__ __half g_w_lo[4][C_DIM * C_DIM];

// ---------------- PTX helpers ---------------------------------------------
__device__ __forceinline__ uint32_t s2u(const void* p) {
    uint32_t a;
    asm("{ .reg .u64 t; cvta.to.shared.u64 t, %1; cvt.u32.u64 %0, t; }" : "=r"(a) : "l"(p));
    return a;
}
__device__ __forceinline__ void cp16(uint32_t s, const void* g) {
    asm volatile("cp.async.cg.shared.global [%0], [%1], 16;" :: "r"(s), "l"(g));
}
__device__ __forceinline__ void cp_commit() { asm volatile("cp.async.commit_group;" ::: "memory"); }
__device__ __forceinline__ void cp_wait1()  { asm volatile("cp.async.wait_group 1;" ::: "memory"); }
__device__ __forceinline__ void cp_wait0()  { asm volatile("cp.async.wait_group 0;" ::: "memory"); }

__device__ __forceinline__ void ldsm4(uint32_t* r, uint32_t addr) {
    asm volatile("ldmatrix.sync.aligned.m8n8.x4.shared.b16 {%0,%1,%2,%3}, [%4];"
        : "=r"(r[0]), "=r"(r[1]), "=r"(r[2]), "=r"(r[3]) : "r"(addr));
}
__device__ __forceinline__ void mma4(float* d, const uint32_t* a, const uint32_t* b) {
    asm volatile("mma.sync.aligned.m16n8k16.row.col.f32.f16.f16.f32 "
        "{%0,%1,%2,%3}, {%4,%5,%6,%7}, {%8,%9}, {%0,%1,%2,%3};"
        : "+f"(d[0]), "+f"(d[1]), "+f"(d[2]), "+f"(d[3])
        : "r"(a[0]), "r"(a[1]), "r"(a[2]), "r"(a[3]), "r"(b[0]), "r"(b[1]));
}

__device__ __forceinline__ void split2(float v0, float v1, __half2& h, __half2& l) {
    __half h0 = __float2half_rn(v0), h1 = __float2half_rn(v1);
    h = __halves2half2(h0, h1);
    l = __halves2half2(__float2half_rn(v0 - __half2float(h0)),
                       __float2half_rn(v1 - __half2float(h1)));
}

// ---------------- CTA GEMM: 128x128 tile, 8 warps, BK=32, split fp16 -------
// TERMS==3: a_hi*b_hi + a_hi*b_lo + a_lo*b_hi; TERMS==2: a_hi*(b_hi+b_lo)
#define TILE_B   10240
#define STAGE_B  40960
#define SMEM_MMA 81920

template<int TERMS>
__device__ __forceinline__ void load_chunk(char* sm, int stage,
    const __half* __restrict__ Ahi, const __half* __restrict__ Alo, int lda,
    const __half* __restrict__ Bhi, const __half* __restrict__ Blo, int ldb,
    int k0, int tid)
{
    uint32_t base = s2u(sm) + stage * STAGE_B;
    const __half* gp[4] = { Ahi + k0, Alo + k0, Bhi + k0, Blo + k0 };
    const int ld[4] = { lda, lda, ldb, ldb };
    #pragma unroll
    for (int t4 = 0; t4 < 4; t4++) {
        if (TERMS == 2 && t4 == 1) continue;   // skip A_lo tile
        #pragma unroll
        for (int it = 0; it < 2; it++) {
            int idx = tid + it * 256;          // 0..511
            int r = idx >> 2, g = idx & 3;     // row, 16B-group
            cp16(base + t4 * TILE_B + r * 80 + g * 16,
                 gp[t4] + (size_t)r * ld[t4] + g * 8);
        }
    }
    cp_commit();
}

template<int TERMS>
__device__ __forceinline__ void compute_chunk(uint32_t sbase, float (&acc)[16][4],
                                              int wm, int wn, int lane)
{
    const int lrow  = (lane & 7) + ((lane & 8) ? 8 : 0);
    const int lcolo = (lane & 16) ? 8 : 0;
    #pragma unroll
    for (int ks = 0; ks < 2; ks++) {
        const int col = ks * 16 + lcolo;
        uint32_t ahi[4][4], alo[4][4], bhi[4][2], blo[4][2];
        #pragma unroll
        for (int mt = 0; mt < 4; mt++) {
            uint32_t off = (uint32_t)(wm * 64 + mt * 16 + lrow) * 80 + col * 2;
            ldsm4(ahi[mt], sbase + off);
            if (TERMS == 3) ldsm4(alo[mt], sbase + TILE_B + off);
        }
        #pragma unroll
        for (int np = 0; np < 2; np++) {
            uint32_t off = (uint32_t)(wn * 32 + np * 16 + lrow) * 80 + col * 2;
            uint32_t th[4], tl[4];
            ldsm4(th, sbase + 2 * TILE_B + off);
            ldsm4(tl, sbase + 3 * TILE_B + off);
            bhi[2*np][0]   = th[0]; bhi[2*np][1]   = th[2];
            bhi[2*np+1][0] = th[1]; bhi[2*np+1][1] = th[3];
            blo[2*np][0]   = tl[0]; blo[2*np][1]   = tl[2];
            blo[2*np+1][0] = tl[1]; blo[2*np+1][1] = tl[3];
        }
        #pragma unroll
        for (int mt = 0; mt < 4; mt++)
            #pragma unroll
            for (int nt = 0; nt < 4; nt++) {
                mma4(acc[mt*4+nt], ahi[mt], bhi[nt]);
                mma4(acc[mt*4+nt], ahi[mt], blo[nt]);
                if (TERMS == 3) mma4(acc[mt*4+nt], alo[mt], bhi[nt]);
            }
    }
}

template<int TERMS>
__device__ void gemm_tile(char* sm,
    const __half* Ahi, const __half* Alo, int lda,
    const __half* Bhi, const __half* Blo, int ldb,
    int K, float (&acc)[16][4])
{
    const int tid = threadIdx.x;
    const int lane = tid & 31, warp = tid >> 5;
    const int wm = warp >> 2, wn = warp & 3;
    #pragma unroll
    for (int f = 0; f < 16; f++)
        acc[f][0] = acc[f][1] = acc[f][2] = acc[f][3] = 0.f;

    const int NC = K >> 5;
    load_chunk<TERMS>(sm, 0, Ahi, Alo, lda, Bhi, Blo, ldb, 0, tid);
    if (NC > 1) load_chunk<TERMS>(sm, 1, Ahi, Alo, lda, Bhi, Blo, ldb, 32, tid);
    const uint32_t smb = s2u(sm);

    for (int c = 0; c < NC; c++) {
        if (c + 1 < NC) cp_wait1(); else cp_wait0();
        __syncthreads();
        compute_chunk<TERMS>(smb + (c & 1) * STAGE_B, acc, wm, wn, lane);
        __syncthreads();
        if (c + 2 < NC)
            load_chunk<TERMS>(sm, c & 1, Ahi, Alo, lda, Bhi, Blo, ldb, (c + 2) * 32, tid);
    }
}

// ---------------- weight convert (all 4 in one launch) --------------------
__global__ void __launch_bounds__(256) convert_w(const float* __restrict__ wq,
                                                 const float* __restrict__ wk,
                                                 const float* __restrict__ wv,
                                                 const float* __restrict__ wo) {
    const int which = blockIdx.y;
    const float* w = (which == 0) ? wq : (which == 1) ? wk : (which == 2) ? wv : wo;
    int i = blockIdx.x * 256 + threadIdx.x;
    float v = w[i];
    __half h = __float2half_rn(v);
    g_w_hi[which][i] = h;
    g_w_lo[which][i] = __float2half_rn(v - __half2float(h));
}

// ---------------- GroupNorm -> h^T split ----------------------------------
__global__ void __launch_bounds__(256) gn_kernel(const float* __restrict__ x,
                                                 const float* __restrict__ sc,
                                                 const float* __restrict__ bi) {
    __shared__ float tile[8][1028];
    __shared__ float red[256], red2[256];
    const int bg = blockIdx.x;
    const int b = bg >> 5, g = bg & 31;
    const float* xb = x + (size_t)b * CN + (size_t)(g * 8) * N_PIX;
    const int t = threadIdx.x;

    float s = 0.f, s2 = 0.f;
    for (int i = t; i < 8 * N_PIX; i += 256) {
        float v = xb[i];
        s += v; s2 += v * v;
    }
    red[t] = s; red2[t] = s2;
    __syncthreads();
    for (int o = 128; o > 0; o >>= 1) {
        if (t < o) { red[t] += red[t + o]; red2[t] += red2[t + o]; }
        __syncthreads();
    }
    const float mean = red[0] * (1.f / 32768.f);
    const float var  = red2[0] * (1.f / 32768.f) - mean * mean;
    const float inv  = rsqrtf(var + EPS);
    float scv[8], biv[8];
    #pragma unroll
    for (int c = 0; c < 8; c++) { scv[c] = sc[g * 8 + c] * inv; biv[c] = bi[g * 8 + c]; }

    for (int p0 = 0; p0 < N_PIX; p0 += 1024) {
        __syncthreads();
        for (int i = t; i < 8192; i += 256) {
            int c = i >> 10, pp = i & 1023;
            tile[c][pp] = xb[(size_t)c * N_PIX + p0 + pp];
        }
        __syncthreads();
        #pragma unroll
        for (int j = 0; j < 4; j++) {
            int p = t + j * 256;
            int ip = p0 + p;
            uint32_t ph[4], pl[4];
            #pragma unroll
            for (int c2 = 0; c2 < 4; c2++) {
                float a  = (tile[2*c2][p]   - mean) * scv[2*c2]   + biv[2*c2];
                float b2 = (tile[2*c2+1][p] - mean) * scv[2*c2+1] + biv[2*c2+1];
                __half2 h, l;
                split2(a, b2, h, l);
                ph[c2] = *(uint32_t*)&h;
                pl[c2] = *(uint32_t*)&l;
            }
            size_t base = ((size_t)b * N_PIX + ip) * C_DIM + g * 8;
            *(uint4*)&g_h_hi[base] = make_uint4(ph[0], ph[1], ph[2], ph[3]);
            *(uint4*)&g_h_lo[base] = make_uint4(pl[0], pl[1], pl[2], pl[3]);
        }
    }
}

// ---------------- q/k projection: D[i,o] = sum_c hT[i,c] w[o,c] -----------
__global__ void __launch_bounds__(256) proj_qk(const float* __restrict__ bq,
                                               const float* __restrict__ bk) {
    extern __shared__ char sm[];
    const int mt_ = blockIdx.x, nt_ = blockIdx.y;
    const int b = blockIdx.z >> 1, p = blockIdx.z & 1;
    const size_t abase = ((size_t)b * N_PIX + mt_ * 128) * C_DIM;
    const __half* Whi = (p ? g_w_hi[1] : g_w_hi[0]) + (size_t)nt_ * 128 * C_DIM;
    const __half* Wlo = (p ? g_w_lo[1] : g_w_lo[0]) + (size_t)nt_ * 128 * C_DIM;

    float acc[16][4];
    gemm_tile<3>(sm, g_h_hi + abase, g_h_lo + abase, C_DIM, Whi, Wlo, C_DIM, C_DIM, acc);

    const float* bias = p ? bk : bq;
    const float scale = p ? 1.0f : 0.0625f;
    __half* Ohi = (p ? g_k_hi : g_q_hi) + abase;
    __half* Olo = (p ? g_k_lo : g_q_lo) + abase;
    const int lane = threadIdx.x & 31, warp = threadIdx.x >> 5;
    const int wm = warp >> 2, wn = warp & 3;
    #pragma unroll
    for (int mt = 0; mt < 4; mt++)
        #pragma unroll
        for (int nt = 0; nt < 4; nt++) {
            const int m = wm * 64 + mt * 16 + (lane >> 2);
            const int n = wn * 32 + nt * 8 + (lane & 3) * 2;
            const int o = nt_ * 128 + n;
            const float b0 = bias[o], b1 = bias[o + 1];
            const float* d = acc[mt * 4 + nt];
            #pragma unroll
            for (int rp = 0; rp < 2; rp++) {
                const int row = m + rp * 8;
                __half2 h, l;
                split2((d[rp*2+0] + b0) * scale, (d[rp*2+1] + b1) * scale, h, l);
                const size_t off = (size_t)row * C_DIM + o;
                *(__half2*)&Ohi[off] = h;
                *(__half2*)&Olo[off] = l;
            }
        }
}

// ---------------- v projection: D[o,i] = sum_c wv[o,c] hT[i,c] ------------
__global__ void __launch_bounds__(256) proj_v(const float* __restrict__ bv) {
    extern __shared__ char sm[];
    const int mt_ = blockIdx.x, nt_ = blockIdx.y, b = blockIdx.z;
    const size_t bbase = ((size_t)b * N_PIX + nt_ * 128) * C_DIM;

    float acc[16][4];
    gemm_tile<2>(sm, g_w_hi[2] + (size_t)mt_ * 128 * C_DIM,
                 g_w_lo[2] + (size_t)mt_ * 128 * C_DIM, C_DIM,
                 g_h_hi + bbase, g_h_lo + bbase, C_DIM, C_DIM, acc);

    const int lane = threadIdx.x & 31, warp = threadIdx.x >> 5;
    const int wm = warp >> 2, wn = warp & 3;
    #pragma unroll
    for (int mt = 0; mt < 4; mt++)
        #pragma unroll
        for (int nt = 0; nt < 4; nt++) {
            const int m = wm * 64 + mt * 16 + (lane >> 2);
            const int n = wn * 32 + nt * 8 + (lane & 3) * 2;
            const int pix = nt_ * 128 + n;
            const float* d = acc[mt * 4 + nt];
            #pragma unroll
            for (int rp = 0; rp < 2; rp++) {
                const int o = mt_ * 128 + m + rp * 8;
                const float bb = bv[o];
                __half2 h, l;
                split2(d[rp*2+0] + bb, d[rp*2+1] + bb, h, l);
                const size_t off = ((size_t)b * C_DIM + o) * N_PIX + pix;
                *(__half2*)&g_v_hi[off] = h;
                *(__half2*)&g_v_lo[off] = l;
            }
        }
}

// ---------------- scores+exp: P[i,j] = exp(sum_c qT[i,c] kT[j,c] - 5) -----
// 2-term: q_hi * (k_hi + k_lo)
__global__ void __launch_bounds__(256) scores_k() {
    extern __shared__ char sm[];
    const int mt_ = blockIdx.x, nt_ = blockIdx.y, b = blockIdx.z;
    const size_t abase = ((size_t)b * N_PIX + mt_ * 128) * C_DIM;
    const size_t bbase = ((size_t)b * N_PIX + nt_ * 128) * C_DIM;

    float acc[16][4];
    gemm_tile<2>(sm, g_q_hi + abase, g_q_lo + abase, C_DIM,
                 g_k_hi + bbase, g_k_lo + bbase, C_DIM, C_DIM, acc);

    __half* Pm = g_p + (size_t)b * NN;
    const int lane = threadIdx.x & 31, warp = threadIdx.x >> 5;
    const int wm = warp >> 2, wn = warp & 3;
    #pragma unroll
    for (int mt = 0; mt < 4; mt++)
        #pragma unroll
        for (int nt = 0; nt < 4; nt++) {
            const int m = wm * 64 + mt * 16 + (lane >> 2);
            const int n = wn * 32 + nt * 8 + (lane & 3) * 2;
            const int j = nt_ * 128 + n;
            const float* d = acc[mt * 4 + nt];
            #pragma unroll
            for (int rp = 0; rp < 2; rp++) {
                const int i = mt_ * 128 + m + rp * 8;
                const float p0 = __expf(d[rp*2+0] - 5.f);
                const float p1 = __expf(d[rp*2+1] - 5.f);
                __half2 hp = __halves2half2(__float2half_rn(p0), __float2half_rn(p1));
                *(__half2*)&Pm[(size_t)i * N_PIX + j] = hp;
            }
        }
}

// ---------------- fused normalize + PV (V hi+lo, 2-term) ------------------
// z[i,c] = (sum_j P[i,j] v[c,j]) / (sum_j P[i,j]),  P fp16 from scores_k.
// 512 threads: warp grid 4x4, warp tile 32 rows x 64 cols. 32-key chunks.
// SMEM: [0,512) rowsum | [512,20992) P 2 stages x 10240 |
//       [20992,102912) V 2 stages x (hi 20480 + lo 20480)
#define SZ_PBASE 512
#define SZ_VBASE 20992
#define SZ_SMEM  102912

__device__ __forceinline__ void sz_load(uint32_t smb, const __half* P,
    const __half* Vhi, const __half* Vlo, int st, int j0, int tid)
{
    uint32_t pb = smb + SZ_PBASE + st * 10240;
    {
        int r = tid >> 2, g = tid & 3;            // i-row, 16B group (32 halves/row)
        cp16(pb + r * 80 + g * 16, P + (size_t)r * N_PIX + j0 + g * 8);
    }
    uint32_t vb = smb + SZ_VBASE + st * 40960;
    #pragma unroll
    for (int it = 0; it < 2; it++) {
        int idx = tid + it * 512;
        int r = idx >> 2, g = idx & 3;            // c-row, 16B group
        size_t go = (size_t)r * N_PIX + j0 + g * 8;
        cp16(vb + r * 80 + g * 16, Vhi + go);
        cp16(vb + 20480 + r * 80 + g * 16, Vlo + go);
    }
    cp_commit();
}

__device__ __forceinline__ void sz_compute(uint32_t sP, uint32_t sVhi, uint32_t sVlo,
                                           float (&acc)[16][4], int wm, int wn, int lane)
{
    const int lrow  = (lane & 7) + ((lane & 8) ? 8 : 0);
    const int lcolo = (lane & 16) ? 8 : 0;
    #pragma unroll
    for (int ks = 0; ks < 2; ks++) {
        const int col = ks * 16 + lcolo;
        uint32_t a[2][4], bhi[8][2], blo[8][2];
        #pragma unroll
        for (int mt = 0; mt < 2; mt++)
            ldsm4(a[mt], sP + (uint32_t)(wm * 32 + mt * 16 + lrow) * 80 + col * 2);
        #pragma unroll
        for (int np = 0; np < 4; np++) {
            uint32_t off = (uint32_t)(wn * 64 + np * 16 + lrow) * 80 + col * 2;
            uint32_t th[4], tl[4];
            ldsm4(th, sVhi + off);
            ldsm4(tl, sVlo + off);
            bhi[2*np][0]   = th[0]; bhi[2*np][1]   = th[2];
            bhi[2*np+1][0] = th[1]; bhi[2*np+1][1] = th[3];
            blo[2*np][0]   = tl[0]; blo[2*np][1]   = tl[2];
            blo[2*np+1][0] = tl[1]; blo[2*np+1][1] = tl[3];
        }
        #pragma unroll
        for (int mt = 0; mt < 2; mt++)
            #pragma unroll
            for (int nt = 0; nt < 8; nt++) {
                mma4(acc[mt*8+nt], a[mt], bhi[nt]);
                mma4(acc[mt*8+nt], a[mt], blo[nt]);
            }
    }
}

__global__ void __launch_bounds__(512, 1) sz_k() {
    extern __shared__ char sm[];
    const int mt_ = blockIdx.x, b = blockIdx.z;
    const int tid = threadIdx.x, lane = tid & 31, warp = tid >> 5;
    const int wm = warp >> 2, wn = warp & 3;
    const uint32_t smb = s2u(sm);

    const __half* P = g_p + (size_t)b * NN + (size_t)(mt_ * 128) * N_PIX;
    const __half* Vhi = g_v_hi + (size_t)b * CN;
    const __half* Vlo = g_v_lo + (size_t)b * CN;

    float acc[16][4];
    #pragma unroll
    for (int f = 0; f < 16; f++)
        acc[f][0] = acc[f][1] = acc[f][2] = acc[f][3] = 0.f;
    float rsum = 0.f;

    const int pr = tid >> 2, pq = tid & 3;        // rowsum: row, 16B quarter

    sz_load(smb, P, Vhi, Vlo, 0, 0, tid);
    sz_load(smb, P, Vhi, Vlo, 1, 32, tid);

    const int NC = N_PIX / 32;   // 128
    for (int c = 0; c < NC; c++) {
        const int st = c & 1;
        if (c + 1 < NC) cp_wait1(); else cp_wait0();
        __syncthreads();
        // ---- row-sum phase: read the staged fp16 P tile (same data MMA uses)
        {
            const uint4 pv = *(const uint4*)(sm + SZ_PBASE + st * 10240 + pr * 80 + pq * 16);
            float2 f0 = __half22float2(*(const __half2*)&pv.x);
            float2 f1 = __half22float2(*(const __half2*)&pv.y);
            float2 f2 = __half22float2(*(const __half2*)&pv.z);
            float2 f3 = __half22float2(*(const __half2*)&pv.w);
            rsum += (f0.x + f0.y) + (f1.x + f1.y) + (f2.x + f2.y) + (f3.x + f3.y);
        }
        sz_compute(smb + SZ_PBASE + st * 10240,
                   smb + SZ_VBASE + st * 40960,
                   smb + SZ_VBASE + st * 40960 + 20480, acc, wm, wn, lane);
        __syncthreads();
        if (c + 2 < NC) sz_load(smb, P, Vhi, Vlo, st, (c + 2) * 32, tid);
    }

    // ---- finalize row sums (4 threads per row -> smem) ----
    rsum += __shfl_xor_sync(0xffffffffu, rsum, 1);
    rsum += __shfl_xor_sync(0xffffffffu, rsum, 2);
    if (pq == 0) ((float*)sm)[pr] = rsum;
    __syncthreads();
    const float* rs = (const float*)sm;

    // ---- epilogue: normalize + split-store z^T ----
    #pragma unroll
    for (int mt = 0; mt < 2; mt++) {
        const int m = wm * 32 + mt * 16 + (lane >> 2);
        const float invA = 1.f / rs[m];
        const float invB = 1.f / rs[m + 8];
        #pragma unroll
        for (int nt = 0; nt < 8; nt++) {
            const int cc = wn * 64 + nt * 8 + (lane & 3) * 2;
            const float* d = acc[mt * 8 + nt];
            __half2 h, l;
            split2(d[0] * invA, d[1] * invA, h, l);
            size_t off = ((size_t)b * N_PIX + mt_ * 128 + m) * C_DIM + cc;
            *(__half2*)&g_z_hi[off] = h;
            *(__half2*)&g_z_lo[off] = l;
            split2(d[2] * invB, d[3] * invB, h, l);
            off = ((size_t)b * N_PIX + mt_ * 128 + m + 8) * C_DIM + cc;
            *(__half2*)&g_z_hi[off] = h;
            *(__half2*)&g_z_lo[off] = l;
        }
    }
}

// ---------------- out: D[o,i] = sum_c wo[o,c] zT[i,c]; + bo + skip --------
__global__ void __launch_bounds__(256) out_k(const float* __restrict__ bo,
                                             const float* __restrict__ x,
                                             float* __restrict__ out) {
    extern __shared__ char sm[];
    const int mt_ = blockIdx.x, nt_ = blockIdx.y, b = blockIdx.z;
    const size_t bbase = ((size_t)b * N_PIX + nt_ * 128) * C_DIM;

    float acc[16][4];
    gemm_tile<2>(sm, g_w_hi[3] + (size_t)mt_ * 128 * C_DIM,
                 g_w_lo[3] + (size_t)mt_ * 128 * C_DIM, C_DIM,
                 g_z_hi + bbase, g_z_lo + bbase, C_DIM, C_DIM, acc);

    const int lane = threadIdx.x & 31, warp = threadIdx.x >> 5;
    const int wm = warp >> 2, wn = warp & 3;
    #pragma unroll
    for (int mt = 0; mt < 4; mt++)
        #pragma unroll
        for (int nt = 0; nt < 4; nt++) {
            const int m = wm * 64 + mt * 16 + (lane >> 2);
            const int n = wn * 32 + nt * 8 + (lane & 3) * 2;
            const int i = nt_ * 128 + n;
            const float* d = acc[mt * 4 + nt];
            #pragma unroll
            for (int rp = 0; rp < 2; rp++) {
                const int o = mt_ * 128 + m + rp * 8;
                const float bb = bo[o];
                const size_t off = ((size_t)b * C_DIM + o) * N_PIX + i;
                float2 sk = *(const float2*)&x[off];
                *(float2*)&out[off] = make_float2(d[rp*2+0] + bb + sk.x,
                                                  d[rp*2+1] + bb + sk.y);
            }
        }
}

// ---------------- launch ---------------------------------------------------
extern "C" void kernel_launch(void* const* d_in, const int* in_sizes, int n_in,
                              void* d_out, int out_size) {
    const float* x  = (const float*)d_in[0];
    const float* gs = (const float*)d_in[1];
    const float* gb = (const float*)d_in[2];
    const float* wq = (const float*)d_in[3];
    const float* bq = (const float*)d_in[4];
    const float* wk = (const float*)d_in[5];
    const float* bk = (const float*)d_in[6];
    const float* wv = (const float*)d_in[7];
    const float* bv = (const float*)d_in[8];
    const float* wo = (const float*)d_in[9];
    const float* bo = (const float*)d_in[10];
    float* out = (float*)d_out;

    cudaFuncSetAttribute(proj_qk,  cudaFuncAttributeMaxDynamicSharedMemorySize, SMEM_MMA);
    cudaFuncSetAttribute(proj_v,   cudaFuncAttributeMaxDynamicSharedMemorySize, SMEM_MMA);
    cudaFuncSetAttribute(scores_k, cudaFuncAttributeMaxDynamicSharedMemorySize, SMEM_MMA);
    cudaFuncSetAttribute(sz_k,     cudaFuncAttributeMaxDynamicSharedMemorySize, SZ_SMEM);
    cudaFuncSetAttribute(out_k,    cudaFuncAttributeMaxDynamicSharedMemorySize, SMEM_MMA);

    convert_w<<<dim3(256, 4), 256>>>(wq, wk, wv, wo);
    gn_kernel<<<B_DIM * 32, 256>>>(x, gs, gb);
    proj_qk<<<dim3(32, 2, B_DIM * 2), 256, SMEM_MMA>>>(bq, bk);
    proj_v<<<dim3(2, 32, B_DIM), 256, SMEM_MMA>>>(bv);
    scores_k<<<dim3(32, 32, B_DIM), 256, SMEM_MMA>>>();
    sz_k<<<dim3(32, 1, B_DIM), 512, SZ_SMEM>>>();
    out_k<<<dim3(2, 32, B_DIM), 256, SMEM_MMA>>>(bo, x, out);
}

// round 16
// speedup vs baseline: 1.2733x; 1.1023x over previous
#include <cuda_runtime.h>
#include <cuda_fp16.h>
#include <stdint.h>
#include <math.h>

#define B_DIM   8
#define C_DIM   256
#define N_PIX   4096
#define EPS     1e-6f
#define CN      ((size_t)C_DIM * N_PIX)
#define NN      ((size_t)N_PIX * N_PIX)

// ---------------- scratch (__device__ globals; no allocation allowed) -----
__device__ __half g_h_hi[(size_t)B_DIM * CN];   // h^T  [B][N][C]
__device__ __half g_h_lo[(size_t)B_DIM * CN];
__device__ __half g_q_hi[(size_t)B_DIM * CN];   // q^T  [B][N][C] (pre-scaled 1/16)
__device__ __half g_q_lo[(size_t)B_DIM * CN];
__device__ __half g_k_hi[(size_t)B_DIM * CN];   // k^T  [B][N][C]
__device__ __half g_k_lo[(size_t)B_DIM * CN];
__device__ __half g_v_hi[(size_t)B_DIM * CN];   // v    [B][C][N]
__device__ __half g_v_lo[(size_t)B_DIM * CN];
__device__ __half g_z_hi[(size_t)B_DIM * CN];   // z^T  [B][N][C]
__device__ __half g_z_lo[(size_t)B_DIM * CN];
__device__ __half g_p  [(size_t)B_DIM * NN];    // P = exp(S - 5), fp16
__device__ __half g_w_hi[4][C_DIM * C_DIM];     // wq, wk, wv, wo
__device__ __half g_w_lo[4][C_DIM * C_DIM];

// ---------------- PTX helpers ---------------------------------------------
__device__ __forceinline__ uint32_t s2u(const void* p) {
    uint32_t a;
    asm("{ .reg .u64 t; cvta.to.shared.u64 t, %1; cvt.u32.u64 %0, t; }" : "=r"(a) : "l"(p));
    return a;
}
__device__ __forceinline__ void cp16(uint32_t s, const void* g) {
    asm volatile("cp.async.cg.shared.global [%0], [%1], 16;" :: "r"(s), "l"(g));
}
__device__ __forceinline__ void cp_commit() { asm volatile("cp.async.commit_group;" ::: "memory"); }
__device__ __forceinline__ void cp_wait1()  { asm volatile("cp.async.wait_group 1;" ::: "memory"); }
__device__ __forceinline__ void cp_wait0()  { asm volatile("cp.async.wait_group 0;" ::: "memory"); }

__device__ __forceinline__ void ldsm4(uint32_t* r, uint32_t addr) {
    asm volatile("ldmatrix.sync.aligned.m8n8.x4.shared.b16 {%0,%1,%2,%3}, [%4];"
        : "=r"(r[0]), "=r"(r[1]), "=r"(r[2]), "=r"(r[3]) : "r"(addr));
}
__device__ __forceinline__ void mma4(float* d, const uint32_t* a, const uint32_t* b) {
    asm volatile("mma.sync.aligned.m16n8k16.row.col.f32.f16.f16.f32 "
        "{%0,%1,%2,%3}, {%4,%5,%6,%7}, {%8,%9}, {%0,%1,%2,%3};"
        : "+f"(d[0]), "+f"(d[1]), "+f"(d[2]), "+f"(d[3])
        : "r"(a[0]), "r"(a[1]), "r"(a[2]), "r"(a[3]), "r"(b[0]), "r"(b[1]));
}

__device__ __forceinline__ void split2(float v0, float v1, __half2& h, __half2& l) {
    __half h0 = __float2half_rn(v0), h1 = __float2half_rn(v1);
    h = __halves2half2(h0, h1);
    l = __halves2half2(__float2half_rn(v0 - __half2float(h0)),
                       __float2half_rn(v1 - __half2float(h1)));
}

// ---------------- CTA GEMM: 128x128 tile, 8 warps, BK=32, split fp16 -------
// TERMS==3: a_hi*b_hi + a_hi*b_lo + a_lo*b_hi; 2 stages, 2 barriers/chunk.
// TERMS==2: a_hi*(b_hi+b_lo); compact stages, 3-deep pipeline, 1 barrier/chunk
//           (load(c+2) hits the stage consumed at c-1, guarded by top barrier).
#define TILE_B 10240
template<int TERMS> struct SCfg;
template<> struct SCfg<3> {
    static const int ALO = 10240, BHI = 20480, BLO = 30720;
    static const int BYTES = 40960, STAGES = 2;
};
template<> struct SCfg<2> {
    static const int ALO = 0, BHI = 10240, BLO = 20480;
    static const int BYTES = 30720, STAGES = 3;
};
#define SMEM_MMA3 (2 * 40960)
#define SMEM_MMA2 (3 * 30720)

template<int TERMS>
__device__ __forceinline__ void load_chunk(char* sm, int stage,
    const __half* __restrict__ Ahi, const __half* __restrict__ Alo, int lda,
    const __half* __restrict__ Bhi, const __half* __restrict__ Blo, int ldb,
    int k0, int tid)
{
    uint32_t base = s2u(sm) + stage * SCfg<TERMS>::BYTES;
    #pragma unroll
    for (int it = 0; it < 2; it++) {
        int idx = tid + it * 256;          // 0..511
        int r = idx >> 2, g = idx & 3;     // row, 16B-group
        uint32_t so = r * 80 + g * 16;
        size_t ga = (size_t)r * lda + k0 + g * 8;
        size_t gb = (size_t)r * ldb + k0 + g * 8;
        cp16(base + so, Ahi + ga);
        if (TERMS == 3) cp16(base + SCfg<TERMS>::ALO + so, Alo + ga);
        cp16(base + SCfg<TERMS>::BHI + so, Bhi + gb);
        cp16(base + SCfg<TERMS>::BLO + so, Blo + gb);
    }
    cp_commit();
}

template<int TERMS>
__device__ __forceinline__ void compute_chunk(uint32_t sbase, float (&acc)[16][4],
                                              int wm, int wn, int lane)
{
    const int lrow  = (lane & 7) + ((lane & 8) ? 8 : 0);
    const int lcolo = (lane & 16) ? 8 : 0;
    #pragma unroll
    for (int ks = 0; ks < 2; ks++) {
        const int col = ks * 16 + lcolo;
        uint32_t ahi[4][4], alo[4][4], bhi[4][2], blo[4][2];
        #pragma unroll
        for (int mt = 0; mt < 4; mt++) {
            uint32_t off = (uint32_t)(wm * 64 + mt * 16 + lrow) * 80 + col * 2;
            ldsm4(ahi[mt], sbase + off);
            if (TERMS == 3) ldsm4(alo[mt], sbase + SCfg<TERMS>::ALO + off);
        }
        #pragma unroll
        for (int np = 0; np < 2; np++) {
            uint32_t off = (uint32_t)(wn * 32 + np * 16 + lrow) * 80 + col * 2;
            uint32_t th[4], tl[4];
            ldsm4(th, sbase + SCfg<TERMS>::BHI + off);
            ldsm4(tl, sbase + SCfg<TERMS>::BLO + off);
            bhi[2*np][0]   = th[0]; bhi[2*np][1]   = th[2];
            bhi[2*np+1][0] = th[1]; bhi[2*np+1][1] = th[3];
            blo[2*np][0]   = tl[0]; blo[2*np][1]   = tl[2];
            blo[2*np+1][0] = tl[1]; blo[2*np+1][1] = tl[3];
        }
        #pragma unroll
        for (int mt = 0; mt < 4; mt++)
            #pragma unroll
            for (int nt = 0; nt < 4; nt++) {
                mma4(acc[mt*4+nt], ahi[mt], bhi[nt]);
                mma4(acc[mt*4+nt], ahi[mt], blo[nt]);
                if (TERMS == 3) mma4(acc[mt*4+nt], alo[mt], bhi[nt]);
            }
    }
}

template<int TERMS>
__device__ void gemm_tile(char* sm,
    const __half* Ahi, const __half* Alo, int lda,
    const __half* Bhi, const __half* Blo, int ldb,
    int K, float (&acc)[16][4])
{
    const int tid = threadIdx.x;
    const int lane = tid & 31, warp = tid >> 5;
    const int wm = warp >> 2, wn = warp & 3;
    #pragma unroll
    for (int f = 0; f < 16; f++)
        acc[f][0] = acc[f][1] = acc[f][2] = acc[f][3] = 0.f;

    const int NC = K >> 5;
    const int NS = SCfg<TERMS>::STAGES;
    load_chunk<TERMS>(sm, 0, Ahi, Alo, lda, Bhi, Blo, ldb, 0, tid);
    if (NC > 1) load_chunk<TERMS>(sm, 1 % NS, Ahi, Alo, lda, Bhi, Blo, ldb, 32, tid);
    const uint32_t smb = s2u(sm);

    for (int c = 0; c < NC; c++) {
        const int st = (NS == 2) ? (c & 1) : (c % 3);
        if (c + 1 < NC) cp_wait1(); else cp_wait0();
        __syncthreads();
        compute_chunk<TERMS>(smb + st * SCfg<TERMS>::BYTES, acc, wm, wn, lane);
        if (NS == 2) __syncthreads();   // 2-stage: guard buffer reuse
        if (c + 2 < NC)
            load_chunk<TERMS>(sm, (c + 2) % NS, Ahi, Alo, lda, Bhi, Blo, ldb,
                              (c + 2) * 32, tid);
    }
}

// ---------------- weight convert (all 4 in one launch) --------------------
__global__ void __launch_bounds__(256) convert_w(const float* __restrict__ wq,
                                                 const float* __restrict__ wk,
                                                 const float* __restrict__ wv,
                                                 const float* __restrict__ wo) {
    const int which = blockIdx.y;
    const float* w = (which == 0) ? wq : (which == 1) ? wk : (which == 2) ? wv : wo;
    int i = blockIdx.x * 256 + threadIdx.x;
    float v = w[i];
    __half h = __float2half_rn(v);
    g_w_hi[which][i] = h;
    g_w_lo[which][i] = __float2half_rn(v - __half2float(h));
}

// ---------------- GroupNorm -> h^T split ----------------------------------
__global__ void __launch_bounds__(256) gn_kernel(const float* __restrict__ x,
                                                 const float* __restrict__ sc,
                                                 const float* __restrict__ bi) {
    __shared__ float tile[8][1028];
    __shared__ float red[256], red2[256];
    const int bg = blockIdx.x;
    const int b = bg >> 5, g = bg & 31;
    const float* xb = x + (size_t)b * CN + (size_t)(g * 8) * N_PIX;
    const int t = threadIdx.x;

    float s = 0.f, s2 = 0.f;
    for (int i = t; i < 8 * N_PIX; i += 256) {
        float v = xb[i];
        s += v; s2 += v * v;
    }
    red[t] = s; red2[t] = s2;
    __syncthreads();
    for (int o = 128; o > 0; o >>= 1) {
        if (t < o) { red[t] += red[t + o]; red2[t] += red2[t + o]; }
        __syncthreads();
    }
    const float mean = red[0] * (1.f / 32768.f);
    const float var  = red2[0] * (1.f / 32768.f) - mean * mean;
    const float inv  = rsqrtf(var + EPS);
    float scv[8], biv[8];
    #pragma unroll
    for (int c = 0; c < 8; c++) { scv[c] = sc[g * 8 + c] * inv; biv[c] = bi[g * 8 + c]; }

    for (int p0 = 0; p0 < N_PIX; p0 += 1024) {
        __syncthreads();
        for (int i = t; i < 8192; i += 256) {
            int c = i >> 10, pp = i & 1023;
            tile[c][pp] = xb[(size_t)c * N_PIX + p0 + pp];
        }
        __syncthreads();
        #pragma unroll
        for (int j = 0; j < 4; j++) {
            int p = t + j * 256;
            int ip = p0 + p;
            uint32_t ph[4], pl[4];
            #pragma unroll
            for (int c2 = 0; c2 < 4; c2++) {
                float a  = (tile[2*c2][p]   - mean) * scv[2*c2]   + biv[2*c2];
                float b2 = (tile[2*c2+1][p] - mean) * scv[2*c2+1] + biv[2*c2+1];
                __half2 h, l;
                split2(a, b2, h, l);
                ph[c2] = *(uint32_t*)&h;
                pl[c2] = *(uint32_t*)&l;
            }
            size_t base = ((size_t)b * N_PIX + ip) * C_DIM + g * 8;
            *(uint4*)&g_h_hi[base] = make_uint4(ph[0], ph[1], ph[2], ph[3]);
            *(uint4*)&g_h_lo[base] = make_uint4(pl[0], pl[1], pl[2], pl[3]);
        }
    }
}

// ---------------- q/k projection: D[i,o] = sum_c hT[i,c] w[o,c] -----------
__global__ void __launch_bounds__(256) proj_qk(const float* __restrict__ bq,
                                               const float* __restrict__ bk) {
    extern __shared__ char sm[];
    const int mt_ = blockIdx.x, nt_ = blockIdx.y;
    const int b = blockIdx.z >> 1, p = blockIdx.z & 1;
    const size_t abase = ((size_t)b * N_PIX + mt_ * 128) * C_DIM;
    const __half* Whi = (p ? g_w_hi[1] : g_w_hi[0]) + (size_t)nt_ * 128 * C_DIM;
    const __half* Wlo = (p ? g_w_lo[1] : g_w_lo[0]) + (size_t)nt_ * 128 * C_DIM;

    float acc[16][4];
    gemm_tile<3>(sm, g_h_hi + abase, g_h_lo + abase, C_DIM, Whi, Wlo, C_DIM, C_DIM, acc);

    const float* bias = p ? bk : bq;
    const float scale = p ? 1.0f : 0.0625f;
    __half* Ohi = (p ? g_k_hi : g_q_hi) + abase;
    __half* Olo = (p ? g_k_lo : g_q_lo) + abase;
    const int lane = threadIdx.x & 31, warp = threadIdx.x >> 5;
    const int wm = warp >> 2, wn = warp & 3;
    #pragma unroll
    for (int mt = 0; mt < 4; mt++)
        #pragma unroll
        for (int nt = 0; nt < 4; nt++) {
            const int m = wm * 64 + mt * 16 + (lane >> 2);
            const int n = wn * 32 + nt * 8 + (lane & 3) * 2;
            const int o = nt_ * 128 + n;
            const float b0 = bias[o], b1 = bias[o + 1];
            const float* d = acc[mt * 4 + nt];
            #pragma unroll
            for (int rp = 0; rp < 2; rp++) {
                const int row = m + rp * 8;
                __half2 h, l;
                split2((d[rp*2+0] + b0) * scale, (d[rp*2+1] + b1) * scale, h, l);
                const size_t off = (size_t)row * C_DIM + o;
                *(__half2*)&Ohi[off] = h;
                *(__half2*)&Olo[off] = l;
            }
        }
}

// ---------------- v projection: D[o,i] = sum_c wv[o,c] hT[i,c] ------------
__global__ void __launch_bounds__(256) proj_v(const float* __restrict__ bv) {
    extern __shared__ char sm[];
    const int mt_ = blockIdx.x, nt_ = blockIdx.y, b = blockIdx.z;
    const size_t bbase = ((size_t)b * N_PIX + nt_ * 128) * C_DIM;

    float acc[16][4];
    gemm_tile<2>(sm, g_w_hi[2] + (size_t)mt_ * 128 * C_DIM,
                 g_w_lo[2] + (size_t)mt_ * 128 * C_DIM, C_DIM,
                 g_h_hi + bbase, g_h_lo + bbase, C_DIM, C_DIM, acc);

    const int lane = threadIdx.x & 31, warp = threadIdx.x >> 5;
    const int wm = warp >> 2, wn = warp & 3;
    #pragma unroll
    for (int mt = 0; mt < 4; mt++)
        #pragma unroll
        for (int nt = 0; nt < 4; nt++) {
            const int m = wm * 64 + mt * 16 + (lane >> 2);
            const int n = wn * 32 + nt * 8 + (lane & 3) * 2;
            const int pix = nt_ * 128 + n;
            const float* d = acc[mt * 4 + nt];
            #pragma unroll
            for (int rp = 0; rp < 2; rp++) {
                const int o = mt_ * 128 + m + rp * 8;
                const float bb = bv[o];
                __half2 h, l;
                split2(d[rp*2+0] + bb, d[rp*2+1] + bb, h, l);
                const size_t off = ((size_t)b * C_DIM + o) * N_PIX + pix;
                *(__half2*)&g_v_hi[off] = h;
                *(__half2*)&g_v_lo[off] = l;
            }
        }
}

// ---------------- scores+exp: P[i,j] = exp(sum_c qT[i,c] kT[j,c] - 5) -----
// 2-term: q_hi * (k_hi + k_lo)
__global__ void __launch_bounds__(256) scores_k() {
    extern __shared__ char sm[];
    const int mt_ = blockIdx.x, nt_ = blockIdx.y, b = blockIdx.z;
    const size_t abase = ((size_t)b * N_PIX + mt_ * 128) * C_DIM;
    const size_t bbase = ((size_t)b * N_PIX + nt_ * 128) * C_DIM;

    float acc[16][4];
    gemm_tile<2>(sm, g_q_hi + abase, g_q_lo + abase, C_DIM,
                 g_k_hi + bbase, g_k_lo + bbase, C_DIM, C_DIM, acc);

    __half* Pm = g_p + (size_t)b * NN;
    const int lane = threadIdx.x & 31, warp = threadIdx.x >> 5;
    const int wm = warp >> 2, wn = warp & 3;
    #pragma unroll
    for (int mt = 0; mt < 4; mt++)
        #pragma unroll
        for (int nt = 0; nt < 4; nt++) {
            const int m = wm * 64 + mt * 16 + (lane >> 2);
            const int n = wn * 32 + nt * 8 + (lane & 3) * 2;
            const int j = nt_ * 128 + n;
            const float* d = acc[mt * 4 + nt];
            #pragma unroll
            for (int rp = 0; rp < 2; rp++) {
                const int i = mt_ * 128 + m + rp * 8;
                const float p0 = __expf(d[rp*2+0] - 5.f);
                const float p1 = __expf(d[rp*2+1] - 5.f);
                __half2 hp = __halves2half2(__float2half_rn(p0), __float2half_rn(p1));
                *(__half2*)&Pm[(size_t)i * N_PIX + j] = hp;
            }
        }
}

// ---------------- fused normalize + PV (V hi+lo, 2-term) ------------------
// z[i,c] = (sum_j P[i,j] v[c,j]) / (sum_j P[i,j]),  P fp16 from scores_k.
// 512 threads: warp grid 4x4, warp tile 32 rows x 64 cols. 32-key chunks.
// 3-stage pipeline, single barrier per chunk (same proof as gemm_tile<2>).
// SMEM: [0,512) rowsum | stages at 512 + st*51200:
//   P +0 (10240) | Vhi +10240 (20480) | Vlo +30720 (20480)
#define SZ_BASE  512
#define SZ_STG   51200
#define SZ_SMEM  (512 + 3 * 51200)

__device__ __forceinline__ void sz_load(uint32_t smb, const __half* P,
    const __half* Vhi, const __half* Vlo, int st, int j0, int tid)
{
    uint32_t sb = smb + SZ_BASE + st * SZ_STG;
    {
        int r = tid >> 2, g = tid & 3;            // i-row, 16B group (32 halves/row)
        cp16(sb + r * 80 + g * 16, P + (size_t)r * N_PIX + j0 + g * 8);
    }
    #pragma unroll
    for (int it = 0; it < 2; it++) {
        int idx = tid + it * 512;
        int r = idx >> 2, g = idx & 3;            // c-row, 16B group
        size_t go = (size_t)r * N_PIX + j0 + g * 8;
        cp16(sb + 10240 + r * 80 + g * 16, Vhi + go);
        cp16(sb + 30720 + r * 80 + g * 16, Vlo + go);
    }
    cp_commit();
}

__device__ __forceinline__ void sz_compute(uint32_t sP, uint32_t sVhi, uint32_t sVlo,
                                           float (&acc)[16][4], int wm, int wn, int lane)
{
    const int lrow  = (lane & 7) + ((lane & 8) ? 8 : 0);
    const int lcolo = (lane & 16) ? 8 : 0;
    #pragma unroll
    for (int ks = 0; ks < 2; ks++) {
        const int col = ks * 16 + lcolo;
        uint32_t a[2][4], bhi[8][2], blo[8][2];
        #pragma unroll
        for (int mt = 0; mt < 2; mt++)
            ldsm4(a[mt], sP + (uint32_t)(wm * 32 + mt * 16 + lrow) * 80 + col * 2);
        #pragma unroll
        for (int np = 0; np < 4; np++) {
            uint32_t off = (uint32_t)(wn * 64 + np * 16 + lrow) * 80 + col * 2;
            uint32_t th[4], tl[4];
            ldsm4(th, sVhi + off);
            ldsm4(tl, sVlo + off);
            bhi[2*np][0]   = th[0]; bhi[2*np][1]   = th[2];
            bhi[2*np+1][0] = th[1]; bhi[2*np+1][1] = th[3];
            blo[2*np][0]   = tl[0]; blo[2*np][1]   = tl[2];
            blo[2*np+1][0] = tl[1]; blo[2*np+1][1] = tl[3];
        }
        #pragma unroll
        for (int mt = 0; mt < 2; mt++)
            #pragma unroll
            for (int nt = 0; nt < 8; nt++) {
                mma4(acc[mt*8+nt], a[mt], bhi[nt]);
                mma4(acc[mt*8+nt], a[mt], blo[nt]);
            }
    }
}

__global__ void __launch_bounds__(512, 1) sz_k() {
    extern __shared__ char sm[];
    const int mt_ = blockIdx.x, b = blockIdx.z;
    const int tid = threadIdx.x, lane = tid & 31, warp = tid >> 5;
    const int wm = warp >> 2, wn = warp & 3;
    const uint32_t smb = s2u(sm);

    const __half* P = g_p + (size_t)b * NN + (size_t)(mt_ * 128) * N_PIX;
    const __half* Vhi = g_v_hi + (size_t)b * CN;
    const __half* Vlo = g_v_lo + (size_t)b * CN;

    float acc[16][4];
    #pragma unroll
    for (int f = 0; f < 16; f++)
        acc[f][0] = acc[f][1] = acc[f][2] = acc[f][3] = 0.f;
    float rsum = 0.f;

    const int pr = tid >> 2, pq = tid & 3;        // rowsum: row, 16B quarter

    sz_load(smb, P, Vhi, Vlo, 0, 0, tid);
    sz_load(smb, P, Vhi, Vlo, 1, 32, tid);

    const int NC = N_PIX / 32;   // 128
    for (int c = 0; c < NC; c++) {
        const int st = c % 3;
        if (c + 1 < NC) cp_wait1(); else cp_wait0();
        __syncthreads();
        // ---- row-sum phase: read the staged fp16 P tile (same data MMA uses)
        {
            const uint4 pv = *(const uint4*)(sm + SZ_BASE + st * SZ_STG + pr * 80 + pq * 16);
            float2 f0 = __half22float2(*(const __half2*)&pv.x);
            float2 f1 = __half22float2(*(const __half2*)&pv.y);
            float2 f2 = __half22float2(*(const __half2*)&pv.z);
            float2 f3 = __half22float2(*(const __half2*)&pv.w);
            rsum += (f0.x + f0.y) + (f1.x + f1.y) + (f2.x + f2.y) + (f3.x + f3.y);
        }
        sz_compute(smb + SZ_BASE + st * SZ_STG,
                   smb + SZ_BASE + st * SZ_STG + 10240,
                   smb + SZ_BASE + st * SZ_STG + 30720, acc, wm, wn, lane);
        if (c + 2 < NC) sz_load(smb, P, Vhi, Vlo, (c + 2) % 3, (c + 2) * 32, tid);
    }

    // ---- finalize row sums (4 threads per row -> smem) ----
    rsum += __shfl_xor_sync(0xffffffffu, rsum, 1);
    rsum += __shfl_xor_sync(0xffffffffu, rsum, 2);
    __syncthreads();
    if (pq == 0) ((float*)sm)[pr] = rsum;
    __syncthreads();
    const float* rs = (const float*)sm;

    // ---- epilogue: normalize + split-store z^T ----
    #pragma unroll
    for (int mt = 0; mt < 2; mt++) {
        const int m = wm * 32 + mt * 16 + (lane >> 2);
        const float invA = 1.f / rs[m];
        const float invB = 1.f / rs[m + 8];
        #pragma unroll
        for (int nt = 0; nt < 8; nt++) {
            const int cc = wn * 64 + nt * 8 + (lane & 3) * 2;
            const float* d = acc[mt * 8 + nt];
            __half2 h, l;
            split2(d[0] * invA, d[1] * invA, h, l);
            size_t off = ((size_t)b * N_PIX + mt_ * 128 + m) * C_DIM + cc;
            *(__half2*)&g_z_hi[off] = h;
            *(__half2*)&g_z_lo[off] = l;
            split2(d[2] * invB, d[3] * invB, h, l);
            off = ((size_t)b * N_PIX + mt_ * 128 + m + 8) * C_DIM + cc;
            *(__half2*)&g_z_hi[off] = h;
            *(__half2*)&g_z_lo[off] = l;
        }
    }
}

// ---------------- out: D[o,i] = sum_c wo[o,c] zT[i,c]; + bo + skip --------
__global__ void __launch_bounds__(256) out_k(const float* __restrict__ bo,
                                             const float* __restrict__ x,
                                             float* __restrict__ out) {
    extern __shared__ char sm[];
    const int mt_ = blockIdx.x, nt_ = blockIdx.y, b = blockIdx.z;
    const size_t bbase = ((size_t)b * N_PIX + nt_ * 128) * C_DIM;

    float acc[16][4];
    gemm_tile<2>(sm, g_w_hi[3] + (size_t)mt_ * 128 * C_DIM,
                 g_w_lo[3] + (size_t)mt_ * 128 * C_DIM, C_DIM,
                 g_z_hi + bbase, g_z_lo + bbase, C_DIM, C_DIM, acc);

    const int lane = threadIdx.x & 31, warp = threadIdx.x >> 5;
    const int wm = warp >> 2, wn = warp & 3;
    #pragma unroll
    for (int mt = 0; mt < 4; mt++)
        #pragma unroll
        for (int nt = 0; nt < 4; nt++) {
            const int m = wm * 64 + mt * 16 + (lane >> 2);
            const int n = wn * 32 + nt * 8 + (lane & 3) * 2;
            const int i = nt_ * 128 + n;
            const float* d = acc[mt * 4 + nt];
            #pragma unroll
            for (int rp = 0; rp < 2; rp++) {
                const int o = mt_ * 128 + m + rp * 8;
                const float bb = bo[o];
                const size_t off = ((size_t)b * C_DIM + o) * N_PIX + i;
                float2 sk = *(const float2*)&x[off];
                *(float2*)&out[off] = make_float2(d[rp*2+0] + bb + sk.x,
                                                  d[rp*2+1] + bb + sk.y);
            }
        }
}

// ---------------- launch ---------------------------------------------------
extern "C" void kernel_launch(void* const* d_in, const int* in_sizes, int n_in,
                              void* d_out, int out_size) {
    const float* x  = (const float*)d_in[0];
    const float* gs = (const float*)d_in[1];
    const float* gb = (const float*)d_in[2];
    const float* wq = (const float*)d_in[3];
    const float* bq = (const float*)d_in[4];
    const float* wk = (const float*)d_in[5];
    const float* bk = (const float*)d_in[6];
    const float* wv = (const float*)d_in[7];
    const float* bv = (const float*)d_in[8];
    const float* wo = (const float*)d_in[9];
    const float* bo = (const float*)d_in[10];
    float* out = (float*)d_out;

    cudaFuncSetAttribute(proj_qk,  cudaFuncAttributeMaxDynamicSharedMemorySize, SMEM_MMA3);
    cudaFuncSetAttribute(proj_v,   cudaFuncAttributeMaxDynamicSharedMemorySize, SMEM_MMA2);
    cudaFuncSetAttribute(scores_k, cudaFuncAttributeMaxDynamicSharedMemorySize, SMEM_MMA2);
    cudaFuncSetAttribute(sz_k,     cudaFuncAttributeMaxDynamicSharedMemorySize, SZ_SMEM);
    cudaFuncSetAttribute(out_k,    cudaFuncAttributeMaxDynamicSharedMemorySize, SMEM_MMA2);

    convert_w<<<dim3(256, 4), 256>>>(wq, wk, wv, wo);
    gn_kernel<<<B_DIM * 32, 256>>>(x, gs, gb);
    proj_qk<<<dim3(32, 2, B_DIM * 2), 256, SMEM_MMA3>>>(bq, bk);
    proj_v<<<dim3(2, 32, B_DIM), 256, SMEM_MMA2>>>(bv);
    scores_k<<<dim3(32, 32, B_DIM), 256, SMEM_MMA2>>>();
    sz_k<<<dim3(32, 1, B_DIM), 512, SZ_SMEM>>>();
    out_k<<<dim3(2, 32, B_DIM), 256, SMEM_MMA2>>>(bo, x, out);
}

// round 17
// speedup vs baseline: 1.3115x; 1.0301x over previous
#include <cuda_runtime.h>
#include <cuda_fp16.h>
#include <stdint.h>
#include <math.h>

#define B_DIM   8
#define C_DIM   256
#define N_PIX   4096
#define EPS     1e-6f
#define CN      ((size_t)C_DIM * N_PIX)
#define NN      ((size_t)N_PIX * N_PIX)

// ---------------- scratch (__device__ globals; no allocation allowed) -----
__device__ __half g_h_hi[(size_t)B_DIM * CN];   // h^T  [B][N][C]
__device__ __half g_h_lo[(size_t)B_DIM * CN];
__device__ __half g_q_hi[(size_t)B_DIM * CN];   // q^T  [B][N][C] (pre-scaled 1/16)
__device__ __half g_q_lo[(size_t)B_DIM * CN];
__device__ __half g_k_hi[(size_t)B_DIM * CN];   // k^T  [B][N][C]
__device__ __half g_k_lo[(size_t)B_DIM * CN];
__device__ __half g_v_hi[(size_t)B_DIM * CN];   // v    [B][C][N]
__device__ __half g_v_lo[(size_t)B_DIM * CN];
__device__ __half g_z_hi[(size_t)B_DIM * CN];   // z^T  [B][N][C]
__device__ __half g_z_lo[(size_t)B_DIM * CN];
__device__ __half g_p  [(size_t)B_DIM * NN];    // P = exp(S - 5), fp16
__device__ __half g_w_hi[4][C_DIM * C_DIM];     // wq, wk, wv, wo
__device__ __half g_w_lo[4][C_DIM * C_DIM];

// ---------------- PTX helpers ---------------------------------------------
__device__ __forceinline__ uint32_t s2u(const void* p) {
    uint32_t a;
    asm("{ .reg .u64 t; cvta.to.shared.u64 t, %1; cvt.u32.u64 %0, t; }" : "=r"(a) : "l"(p));
    return a;
}
__device__ __forceinline__ void cp16(uint32_t s, const void* g) {
    asm volatile("cp.async.cg.shared.global [%0], [%1], 16;" :: "r"(s), "l"(g));
}
__device__ __forceinline__ void cp_commit() { asm volatile("cp.async.commit_group;" ::: "memory"); }
__device__ __forceinline__ void cp_wait1()  { asm volatile("cp.async.wait_group 1;" ::: "memory"); }
__device__ __forceinline__ void cp_wait0()  { asm volatile("cp.async.wait_group 0;" ::: "memory"); }

__device__ __forceinline__ void ldsm4(uint32_t* r, uint32_t addr) {
    asm volatile("ldmatrix.sync.aligned.m8n8.x4.shared.b16 {%0,%1,%2,%3}, [%4];"
        : "=r"(r[0]), "=r"(r[1]), "=r"(r[2]), "=r"(r[3]) : "r"(addr));
}
__device__ __forceinline__ void mma4(float* d, const uint32_t* a, const uint32_t* b) {
    asm volatile("mma.sync.aligned.m16n8k16.row.col.f32.f16.f16.f32 "
        "{%0,%1,%2,%3}, {%4,%5,%6,%7}, {%8,%9}, {%0,%1,%2,%3};"
        : "+f"(d[0]), "+f"(d[1]), "+f"(d[2]), "+f"(d[3])
        : "r"(a[0]), "r"(a[1]), "r"(a[2]), "r"(a[3]), "r"(b[0]), "r"(b[1]));
}

__device__ __forceinline__ void split2(float v0, float v1, __half2& h, __half2& l) {
    __half h0 = __float2half_rn(v0), h1 = __float2half_rn(v1);
    h = __halves2half2(h0, h1);
    l = __halves2half2(__float2half_rn(v0 - __half2float(h0)),
                       __float2half_rn(v1 - __half2float(h1)));
}

// ---------------- CTA GEMM: 128x128 tile, 8 warps, BK=32, split fp16 -------
// TERMS==3: a_hi*b_hi + a_hi*b_lo + a_lo*b_hi; 2 stages, 2 barriers/chunk.
// TERMS==2: a_hi*(b_hi+b_lo); compact stages, 3-deep pipeline, 1 barrier/chunk
//           (load(c+2) hits the stage consumed at c-1, guarded by top barrier).
#define TILE_B 10240
template<int TERMS> struct SCfg;
template<> struct SCfg<3> {
    static const int ALO = 10240, BHI = 20480, BLO = 30720;
    static const int BYTES = 40960, STAGES = 2;
};
template<> struct SCfg<2> {
    static const int ALO = 0, BHI = 10240, BLO = 20480;
    static const int BYTES = 30720, STAGES = 3;
};
#define SMEM_MMA3 (2 * 40960)
#define SMEM_MMA2 (3 * 30720)

template<int TERMS>
__device__ __forceinline__ void load_chunk(char* sm, int stage,
    const __half* __restrict__ Ahi, const __half* __restrict__ Alo, int lda,
    const __half* __restrict__ Bhi, const __half* __restrict__ Blo, int ldb,
    int k0, int tid)
{
    uint32_t base = s2u(sm) + stage * SCfg<TERMS>::BYTES;
    #pragma unroll
    for (int it = 0; it < 2; it++) {
        int idx = tid + it * 256;          // 0..511
        int r = idx >> 2, g = idx & 3;     // row, 16B-group
        uint32_t so = r * 80 + g * 16;
        size_t ga = (size_t)r * lda + k0 + g * 8;
        size_t gb = (size_t)r * ldb + k0 + g * 8;
        cp16(base + so, Ahi + ga);
        if (TERMS == 3) cp16(base + SCfg<TERMS>::ALO + so, Alo + ga);
        cp16(base + SCfg<TERMS>::BHI + so, Bhi + gb);
        cp16(base + SCfg<TERMS>::BLO + so, Blo + gb);
    }
    cp_commit();
}

template<int TERMS>
__device__ __forceinline__ void compute_chunk(uint32_t sbase, float (&acc)[16][4],
                                              int wm, int wn, int lane)
{
    const int lrow  = (lane & 7) + ((lane & 8) ? 8 : 0);
    const int lcolo = (lane & 16) ? 8 : 0;
    #pragma unroll
    for (int ks = 0; ks < 2; ks++) {
        const int col = ks * 16 + lcolo;
        uint32_t ahi[4][4], alo[4][4], bhi[4][2], blo[4][2];
        #pragma unroll
        for (int mt = 0; mt < 4; mt++) {
            uint32_t off = (uint32_t)(wm * 64 + mt * 16 + lrow) * 80 + col * 2;
            ldsm4(ahi[mt], sbase + off);
            if (TERMS == 3) ldsm4(alo[mt], sbase + SCfg<TERMS>::ALO + off);
        }
        #pragma unroll
        for (int np = 0; np < 2; np++) {
            uint32_t off = (uint32_t)(wn * 32 + np * 16 + lrow) * 80 + col * 2;
            uint32_t th[4], tl[4];
            ldsm4(th, sbase + SCfg<TERMS>::BHI + off);
            ldsm4(tl, sbase + SCfg<TERMS>::BLO + off);
            bhi[2*np][0]   = th[0]; bhi[2*np][1]   = th[2];
            bhi[2*np+1][0] = th[1]; bhi[2*np+1][1] = th[3];
            blo[2*np][0]   = tl[0]; blo[2*np][1]   = tl[2];
            blo[2*np+1][0] = tl[1]; blo[2*np+1][1] = tl[3];
        }
        #pragma unroll
        for (int mt = 0; mt < 4; mt++)
            #pragma unroll
            for (int nt = 0; nt < 4; nt++) {
                mma4(acc[mt*4+nt], ahi[mt], bhi[nt]);
                mma4(acc[mt*4+nt], ahi[mt], blo[nt]);
                if (TERMS == 3) mma4(acc[mt*4+nt], alo[mt], bhi[nt]);
            }
    }
}

template<int TERMS>
__device__ void gemm_tile(char* sm,
    const __half* Ahi, const __half* Alo, int lda,
    const __half* Bhi, const __half* Blo, int ldb,
    int K, float (&acc)[16][4])
{
    const int tid = threadIdx.x;
    const int lane = tid & 31, warp = tid >> 5;
    const int wm = warp >> 2, wn = warp & 3;
    #pragma unroll
    for (int f = 0; f < 16; f++)
        acc[f][0] = acc[f][1] = acc[f][2] = acc[f][3] = 0.f;

    const int NC = K >> 5;
    const int NS = SCfg<TERMS>::STAGES;
    load_chunk<TERMS>(sm, 0, Ahi, Alo, lda, Bhi, Blo, ldb, 0, tid);
    if (NC > 1) load_chunk<TERMS>(sm, 1 % NS, Ahi, Alo, lda, Bhi, Blo, ldb, 32, tid);
    const uint32_t smb = s2u(sm);

    for (int c = 0; c < NC; c++) {
        const int st = (NS == 2) ? (c & 1) : (c % 3);
        if (c + 1 < NC) cp_wait1(); else cp_wait0();
        __syncthreads();
        compute_chunk<TERMS>(smb + st * SCfg<TERMS>::BYTES, acc, wm, wn, lane);
        if (NS == 2) __syncthreads();   // 2-stage: guard buffer reuse
        if (c + 2 < NC)
            load_chunk<TERMS>(sm, (c + 2) % NS, Ahi, Alo, lda, Bhi, Blo, ldb,
                              (c + 2) * 32, tid);
    }
}

// ---------------- weight convert (all 4 in one launch) --------------------
__global__ void __launch_bounds__(256) convert_w(const float* __restrict__ wq,
                                                 const float* __restrict__ wk,
                                                 const float* __restrict__ wv,
                                                 const float* __restrict__ wo) {
    const int which = blockIdx.y;
    const float* w = (which == 0) ? wq : (which == 1) ? wk : (which == 2) ? wv : wo;
    int i = blockIdx.x * 256 + threadIdx.x;
    float v = w[i];
    __half h = __float2half_rn(v);
    g_w_hi[which][i] = h;
    g_w_lo[which][i] = __float2half_rn(v - __half2float(h));
}

// ---------------- GroupNorm -> h^T split ----------------------------------
__global__ void __launch_bounds__(256) gn_kernel(const float* __restrict__ x,
                                                 const float* __restrict__ sc,
                                                 const float* __restrict__ bi) {
    __shared__ float tile[8][1028];
    __shared__ float red[256], red2[256];
    const int bg = blockIdx.x;
    const int b = bg >> 5, g = bg & 31;
    const float* xb = x + (size_t)b * CN + (size_t)(g * 8) * N_PIX;
    const int t = threadIdx.x;

    float s = 0.f, s2 = 0.f;
    for (int i = t; i < 8 * N_PIX; i += 256) {
        float v = xb[i];
        s += v; s2 += v * v;
    }
    red[t] = s; red2[t] = s2;
    __syncthreads();
    for (int o = 128; o > 0; o >>= 1) {
        if (t < o) { red[t] += red[t + o]; red2[t] += red2[t + o]; }
        __syncthreads();
    }
    const float mean = red[0] * (1.f / 32768.f);
    const float var  = red2[0] * (1.f / 32768.f) - mean * mean;
    const float inv  = rsqrtf(var + EPS);
    float scv[8], biv[8];
    #pragma unroll
    for (int c = 0; c < 8; c++) { scv[c] = sc[g * 8 + c] * inv; biv[c] = bi[g * 8 + c]; }

    for (int p0 = 0; p0 < N_PIX; p0 += 1024) {
        __syncthreads();
        for (int i = t; i < 8192; i += 256) {
            int c = i >> 10, pp = i & 1023;
            tile[c][pp] = xb[(size_t)c * N_PIX + p0 + pp];
        }
        __syncthreads();
        #pragma unroll
        for (int j = 0; j < 4; j++) {
            int p = t + j * 256;
            int ip = p0 + p;
            uint32_t ph[4], pl[4];
            #pragma unroll
            for (int c2 = 0; c2 < 4; c2++) {
                float a  = (tile[2*c2][p]   - mean) * scv[2*c2]   + biv[2*c2];
                float b2 = (tile[2*c2+1][p] - mean) * scv[2*c2+1] + biv[2*c2+1];
                __half2 h, l;
                split2(a, b2, h, l);
                ph[c2] = *(uint32_t*)&h;
                pl[c2] = *(uint32_t*)&l;
            }
            size_t base = ((size_t)b * N_PIX + ip) * C_DIM + g * 8;
            *(uint4*)&g_h_hi[base] = make_uint4(ph[0], ph[1], ph[2], ph[3]);
            *(uint4*)&g_h_lo[base] = make_uint4(pl[0], pl[1], pl[2], pl[3]);
        }
    }
}

// ---------------- q/k projection: D[i,o] = sum_c hT[i,c] w[o,c] -----------
// 2-term: h_hi * (w_hi + w_lo). q_lo is dead (scores is 2-term on q side)
// but stored anyway to keep the epilogue uniform with k (k_lo IS consumed).
__global__ void __launch_bounds__(256) proj_qk(const float* __restrict__ bq,
                                               const float* __restrict__ bk) {
    extern __shared__ char sm[];
    const int mt_ = blockIdx.x, nt_ = blockIdx.y;
    const int b = blockIdx.z >> 1, p = blockIdx.z & 1;
    const size_t abase = ((size_t)b * N_PIX + mt_ * 128) * C_DIM;
    const __half* Whi = (p ? g_w_hi[1] : g_w_hi[0]) + (size_t)nt_ * 128 * C_DIM;
    const __half* Wlo = (p ? g_w_lo[1] : g_w_lo[0]) + (size_t)nt_ * 128 * C_DIM;

    float acc[16][4];
    gemm_tile<2>(sm, g_h_hi + abase, g_h_lo + abase, C_DIM, Whi, Wlo, C_DIM, C_DIM, acc);

    const float* bias = p ? bk : bq;
    const float scale = p ? 1.0f : 0.0625f;
    __half* Ohi = (p ? g_k_hi : g_q_hi) + abase;
    __half* Olo = (p ? g_k_lo : g_q_lo) + abase;
    const int lane = threadIdx.x & 31, warp = threadIdx.x >> 5;
    const int wm = warp >> 2, wn = warp & 3;
    #pragma unroll
    for (int mt = 0; mt < 4; mt++)
        #pragma unroll
        for (int nt = 0; nt < 4; nt++) {
            const int m = wm * 64 + mt * 16 + (lane >> 2);
            const int n = wn * 32 + nt * 8 + (lane & 3) * 2;
            const int o = nt_ * 128 + n;
            const float b0 = bias[o], b1 = bias[o + 1];
            const float* d = acc[mt * 4 + nt];
            #pragma unroll
            for (int rp = 0; rp < 2; rp++) {
                const int row = m + rp * 8;
                __half2 h, l;
                split2((d[rp*2+0] + b0) * scale, (d[rp*2+1] + b1) * scale, h, l);
                const size_t off = (size_t)row * C_DIM + o;
                *(__half2*)&Ohi[off] = h;
                *(__half2*)&Olo[off] = l;
            }
        }
}

// ---------------- v projection: D[o,i] = sum_c wv[o,c] hT[i,c] ------------
__global__ void __launch_bounds__(256) proj_v(const float* __restrict__ bv) {
    extern __shared__ char sm[];
    const int mt_ = blockIdx.x, nt_ = blockIdx.y, b = blockIdx.z;
    const size_t bbase = ((size_t)b * N_PIX + nt_ * 128) * C_DIM;

    float acc[16][4];
    gemm_tile<2>(sm, g_w_hi[2] + (size_t)mt_ * 128 * C_DIM,
                 g_w_lo[2] + (size_t)mt_ * 128 * C_DIM, C_DIM,
                 g_h_hi + bbase, g_h_lo + bbase, C_DIM, C_DIM, acc);

    const int lane = threadIdx.x & 31, warp = threadIdx.x >> 5;
    const int wm = warp >> 2, wn = warp & 3;
    #pragma unroll
    for (int mt = 0; mt < 4; mt++)
        #pragma unroll
        for (int nt = 0; nt < 4; nt++) {
            const int m = wm * 64 + mt * 16 + (lane >> 2);
            const int n = wn * 32 + nt * 8 + (lane & 3) * 2;
            const int pix = nt_ * 128 + n;
            const float* d = acc[mt * 4 + nt];
            #pragma unroll
            for (int rp = 0; rp < 2; rp++) {
                const int o = mt_ * 128 + m + rp * 8;
                const float bb = bv[o];
                __half2 h, l;
                split2(d[rp*2+0] + bb, d[rp*2+1] + bb, h, l);
                const size_t off = ((size_t)b * C_DIM + o) * N_PIX + pix;
                *(__half2*)&g_v_hi[off] = h;
                *(__half2*)&g_v_lo[off] = l;
            }
        }
}

// ---------------- scores+exp: P[i,j] = exp(sum_c qT[i,c] kT[j,c] - 5) -----
// 2-term: q_hi * (k_hi + k_lo)
__global__ void __launch_bounds__(256) scores_k() {
    extern __shared__ char sm[];
    const int mt_ = blockIdx.x, nt_ = blockIdx.y, b = blockIdx.z;
    const size_t abase = ((size_t)b * N_PIX + mt_ * 128) * C_DIM;
    const size_t bbase = ((size_t)b * N_PIX + nt_ * 128) * C_DIM;

    float acc[16][4];
    gemm_tile<2>(sm, g_q_hi + abase, g_q_lo + abase, C_DIM,
                 g_k_hi + bbase, g_k_lo + bbase, C_DIM, C_DIM, acc);

    __half* Pm = g_p + (size_t)b * NN;
    const int lane = threadIdx.x & 31, warp = threadIdx.x >> 5;
    const int wm = warp >> 2, wn = warp & 3;
    #pragma unroll
    for (int mt = 0; mt < 4; mt++)
        #pragma unroll
        for (int nt = 0; nt < 4; nt++) {
            const int m = wm * 64 + mt * 16 + (lane >> 2);
            const int n = wn * 32 + nt * 8 + (lane & 3) * 2;
            const int j = nt_ * 128 + n;
            const float* d = acc[mt * 4 + nt];
            #pragma unroll
            for (int rp = 0; rp < 2; rp++) {
                const int i = mt_ * 128 + m + rp * 8;
                const float p0 = __expf(d[rp*2+0] - 5.f);
                const float p1 = __expf(d[rp*2+1] - 5.f);
                __half2 hp = __halves2half2(__float2half_rn(p0), __float2half_rn(p1));
                *(__half2*)&Pm[(size_t)i * N_PIX + j] = hp;
            }
        }
}

// ---------------- fused normalize + PV (V hi+lo, 2-term) ------------------
// z[i,c] = (sum_j P[i,j] v[c,j]) / (sum_j P[i,j]),  P fp16 from scores_k.
// 512 threads: warp grid 4x4, warp tile 32 rows x 64 cols. 32-key chunks.
// 3-stage pipeline, single barrier per chunk (same proof as gemm_tile<2>).
// SMEM: [0,512) rowsum | stages at 512 + st*51200:
//   P +0 (10240) | Vhi +10240 (20480) | Vlo +30720 (20480)
#define SZ_BASE  512
#define SZ_STG   51200
#define SZ_SMEM  (512 + 3 * 51200)

__device__ __forceinline__ void sz_load(uint32_t smb, const __half* P,
    const __half* Vhi, const __half* Vlo, int st, int j0, int tid)
{
    uint32_t sb = smb + SZ_BASE + st * SZ_STG;
    {
        int r = tid >> 2, g = tid & 3;            // i-row, 16B group (32 halves/row)
        cp16(sb + r * 80 + g * 16, P + (size_t)r * N_PIX + j0 + g * 8);
    }
    #pragma unroll
    for (int it = 0; it < 2; it++) {
        int idx = tid + it * 512;
        int r = idx >> 2, g = idx & 3;            // c-row, 16B group
        size_t go = (size_t)r * N_PIX + j0 + g * 8;
        cp16(sb + 10240 + r * 80 + g * 16, Vhi + go);
        cp16(sb + 30720 + r * 80 + g * 16, Vlo + go);
    }
    cp_commit();
}

__device__ __forceinline__ void sz_compute(uint32_t sP, uint32_t sVhi, uint32_t sVlo,
                                           float (&acc)[16][4], int wm, int wn, int lane)
{
    const int lrow  = (lane & 7) + ((lane & 8) ? 8 : 0);
    const int lcolo = (lane & 16) ? 8 : 0;
    #pragma unroll
    for (int ks = 0; ks < 2; ks++) {
        const int col = ks * 16 + lcolo;
        uint32_t a[2][4], bhi[8][2], blo[8][2];
        #pragma unroll
        for (int mt = 0; mt < 2; mt++)
            ldsm4(a[mt], sP + (uint32_t)(wm * 32 + mt * 16 + lrow) * 80 + col * 2);
        #pragma unroll
        for (int np = 0; np < 4; np++) {
            uint32_t off = (uint32_t)(wn * 64 + np * 16 + lrow) * 80 + col * 2;
            uint32_t th[4], tl[4];
            ldsm4(th, sVhi + off);
            ldsm4(tl, sVlo + off);
            bhi[2*np][0]   = th[0]; bhi[2*np][1]   = th[2];
            bhi[2*np+1][0] = th[1]; bhi[2*np+1][1] = th[3];
            blo[2*np][0]   = tl[0]; blo[2*np][1]   = tl[2];
            blo[2*np+1][0] = tl[1]; blo[2*np+1][1] = tl[3];
        }
        #pragma unroll
        for (int mt = 0; mt < 2; mt++)
            #pragma unroll
            for (int nt = 0; nt < 8; nt++) {
                mma4(acc[mt*8+nt], a[mt], bhi[nt]);
                mma4(acc[mt*8+nt], a[mt], blo[nt]);
            }
    }
}

__global__ void __launch_bounds__(512, 1) sz_k() {
    extern __shared__ char sm[];
    const int mt_ = blockIdx.x, b = blockIdx.z;
    const int tid = threadIdx.x, lane = tid & 31, warp = tid >> 5;
    const int wm = warp >> 2, wn = warp & 3;
    const uint32_t smb = s2u(sm);

    const __half* P = g_p + (size_t)b * NN + (size_t)(mt_ * 128) * N_PIX;
    const __half* Vhi = g_v_hi + (size_t)b * CN;
    const __half* Vlo = g_v_lo + (size_t)b * CN;

    float acc[16][4];
    #pragma unroll
    for (int f = 0; f < 16; f++)
        acc[f][0] = acc[f][1] = acc[f][2] = acc[f][3] = 0.f;
    float rsum = 0.f;

    const int pr = tid >> 2, pq = tid & 3;        // rowsum: row, 16B quarter

    sz_load(smb, P, Vhi, Vlo, 0, 0, tid);
    sz_load(smb, P, Vhi, Vlo, 1, 32, tid);

    const int NC = N_PIX / 32;   // 128
    for (int c = 0; c < NC; c++) {
        const int st = c % 3;
        if (c + 1 < NC) cp_wait1(); else cp_wait0();
        __syncthreads();
        // ---- row-sum phase: read the staged fp16 P tile (same data MMA uses)
        {
            const uint4 pv = *(const uint4*)(sm + SZ_BASE + st * SZ_STG + pr * 80 + pq * 16);
            float2 f0 = __half22float2(*(const __half2*)&pv.x);
            float2 f1 = __half22float2(*(const __half2*)&pv.y);
            float2 f2 = __half22float2(*(const __half2*)&pv.z);
            float2 f3 = __half22float2(*(const __half2*)&pv.w);
            rsum += (f0.x + f0.y) + (f1.x + f1.y) + (f2.x + f2.y) + (f3.x + f3.y);
        }
        sz_compute(smb + SZ_BASE + st * SZ_STG,
                   smb + SZ_BASE + st * SZ_STG + 10240,
                   smb + SZ_BASE + st * SZ_STG + 30720, acc, wm, wn, lane);
        if (c + 2 < NC) sz_load(smb, P, Vhi, Vlo, (c + 2) % 3, (c + 2) * 32, tid);
    }

    // ---- finalize row sums (4 threads per row -> smem) ----
    rsum += __shfl_xor_sync(0xffffffffu, rsum, 1);
    rsum += __shfl_xor_sync(0xffffffffu, rsum, 2);
    __syncthreads();
    if (pq == 0) ((float*)sm)[pr] = rsum;
    __syncthreads();
    const float* rs = (const float*)sm;

    // ---- epilogue: normalize + split-store z^T ----
    #pragma unroll
    for (int mt = 0; mt < 2; mt++) {
        const int m = wm * 32 + mt * 16 + (lane >> 2);
        const float invA = 1.f / rs[m];
        const float invB = 1.f / rs[m + 8];
        #pragma unroll
        for (int nt = 0; nt < 8; nt++) {
            const int cc = wn * 64 + nt * 8 + (lane & 3) * 2;
            const float* d = acc[mt * 8 + nt];
            __half2 h, l;
            split2(d[0] * invA, d[1] * invA, h, l);
            size_t off = ((size_t)b * N_PIX + mt_ * 128 + m) * C_DIM + cc;
            *(__half2*)&g_z_hi[off] = h;
            *(__half2*)&g_z_lo[off] = l;
            split2(d[2] * invB, d[3] * invB, h, l);
            off = ((size_t)b * N_PIX + mt_ * 128 + m + 8) * C_DIM + cc;
            *(__half2*)&g_z_hi[off] = h;
            *(__half2*)&g_z_lo[off] = l;
        }
    }
}

// ---------------- out: D[o,i] = sum_c wo[o,c] zT[i,c]; + bo + skip --------
__global__ void __launch_bounds__(256) out_k(const float* __restrict__ bo,
                                             const float* __restrict__ x,
                                             float* __restrict__ out) {
    extern __shared__ char sm[];
    const int mt_ = blockIdx.x, nt_ = blockIdx.y, b = blockIdx.z;
    const size_t bbase = ((size_t)b * N_PIX + nt_ * 128) * C_DIM;

    float acc[16][4];
    gemm_tile<2>(sm, g_w_hi[3] + (size_t)mt_ * 128 * C_DIM,
                 g_w_lo[3] + (size_t)mt_ * 128 * C_DIM, C_DIM,
                 g_z_hi + bbase, g_z_lo + bbase, C_DIM, C_DIM, acc);

    const int lane = threadIdx.x & 31, warp = threadIdx.x >> 5;
    const int wm = warp >> 2, wn = warp & 3;
    #pragma unroll
    for (int mt = 0; mt < 4; mt++)
        #pragma unroll
        for (int nt = 0; nt < 4; nt++) {
            const int m = wm * 64 + mt * 16 + (lane >> 2);
            const int n = wn * 32 + nt * 8 + (lane & 3) * 2;
            const int i = nt_ * 128 + n;
            const float* d = acc[mt * 4 + nt];
            #pragma unroll
            for (int rp = 0; rp < 2; rp++) {
                const int o = mt_ * 128 + m + rp * 8;
                const float bb = bo[o];
                const size_t off = ((size_t)b * C_DIM + o) * N_PIX + i;
                float2 sk = *(const float2*)&x[off];
                *(float2*)&out[off] = make_float2(d[rp*2+0] + bb + sk.x,
                                                  d[rp*2+1] + bb + sk.y);
            }
        }
}

// ---------------- launch ---------------------------------------------------
extern "C" void kernel_launch(void* const* d_in, const int* in_sizes, int n_in,
                              void* d_out, int out_size) {
    const float* x  = (const float*)d_in[0];
    const float* gs = (const float*)d_in[1];
    const float* gb = (const float*)d_in[2];
    const float* wq = (const float*)d_in[3];
    const float* bq = (const float*)d_in[4];
    const float* wk = (const float*)d_in[5];
    const float* bk = (const float*)d_in[6];
    const float* wv = (const float*)d_in[7];
    const float* bv = (const float*)d_in[8];
    const float* wo = (const float*)d_in[9];
    const float* bo = (const float*)d_in[10];
    float* out = (float*)d_out;

    cudaFuncSetAttribute(proj_qk,  cudaFuncAttributeMaxDynamicSharedMemorySize, SMEM_MMA2);
    cudaFuncSetAttribute(proj_v,   cudaFuncAttributeMaxDynamicSharedMemorySize, SMEM_MMA2);
    cudaFuncSetAttribute(scores_k, cudaFuncAttributeMaxDynamicSharedMemorySize, SMEM_MMA2);
    cudaFuncSetAttribute(sz_k,     cudaFuncAttributeMaxDynamicSharedMemorySize, SZ_SMEM);
    cudaFuncSetAttribute(out_k,    cudaFuncAttributeMaxDynamicSharedMemorySize, SMEM_MMA2);

    convert_w<<<dim3(256, 4), 256>>>(wq, wk, wv, wo);
    gn_kernel<<<B_DIM * 32, 256>>>(x, gs, gb);
    proj_qk<<<dim3(32, 2, B_DIM * 2), 256, SMEM_MMA2>>>(bq, bk);
    proj_v<<<dim3(2, 32, B_DIM), 256, SMEM_MMA2>>>(bv);
    scores_k<<<dim3(32, 32, B_DIM), 256, SMEM_MMA2>>>();
    sz_k<<<dim3(32, 1, B_DIM), 512, SZ_SMEM>>>();
    out_k<<<dim3(2, 32, B_DIM), 256, SMEM_MMA2>>>(bo, x, out);
}